// round 4
// baseline (speedup 1.0000x reference)
#include <cuda_runtime.h>
#include <cstddef>
#include <cstdint>

#define Hdim 1024
#define NHnum 16
#define DHdim 64
#define Bb 4
#define Tfull 1024
#define DINc 2304
#define Ff 4096
#define HH (1024*1024)

// ------------------------- scratch (device globals) -------------------------
__device__ float g_xT [(size_t)Bb*Tfull*DINc];
__device__ float g_wTe[(size_t)3*DINc*Hdim];
__device__ float g_wTc[(size_t)3*Hdim*Hdim];
__device__ float g_wTd[(size_t)3*3*Hdim*Hdim];
__device__ float g_bufX [(size_t)Bb*Tfull*Hdim];
__device__ float g_bufQ [(size_t)Bb*Tfull*Hdim];
__device__ float g_bufK [(size_t)Bb*Tfull*Hdim];
__device__ float g_bufV [(size_t)Bb*Tfull*Hdim];
__device__ float g_bufA [(size_t)Bb*Tfull*Hdim];
__device__ float g_bufT [(size_t)Bb*Tfull*Hdim];
__device__ float g_bufY [(size_t)Bb*Tfull*Hdim];
__device__ float g_bufD [(size_t)Bb*Tfull*Hdim];
__device__ float g_bufY2[(size_t)Bb*Tfull*Hdim];
__device__ float g_bufZ [(size_t)Bb*Tfull*Hdim];
__device__ float g_bufF [(size_t)Bb*Tfull*Ff];

// ------------------------- transposes -------------------------
__global__ void transpose2d_kernel(float* __restrict__ dst, const float* __restrict__ src,
                                   int R, int C)
{
    __shared__ float tile[32][33];
    int b = blockIdx.z;
    const float* s = src + (size_t)b * R * C;
    float* d = dst + (size_t)b * R * C;
    int c0 = blockIdx.x * 32, r0 = blockIdx.y * 32;
    int tx = threadIdx.x, ty = threadIdx.y;
    #pragma unroll
    for (int i = 0; i < 32; i += 8)
        tile[ty + i][tx] = s[(size_t)(r0 + ty + i) * C + c0 + tx];
    __syncthreads();
    #pragma unroll
    for (int i = 0; i < 32; i += 8)
        d[(size_t)(c0 + ty + i) * R + r0 + tx] = tile[tx][ty + i];
}

__global__ void transpose_convw_kernel(float* __restrict__ dst, const float* __restrict__ src,
                                       int Hout, int Cin)
{
    __shared__ float tile[32][33];
    int k = blockIdx.z;
    int c0 = blockIdx.x * 32, h0 = blockIdx.y * 32;
    int tx = threadIdx.x, ty = threadIdx.y;
    #pragma unroll
    for (int i = 0; i < 32; i += 8)
        tile[tx][ty + i] = src[((size_t)(h0 + ty + i) * Cin + c0 + tx) * 3 + k];
    __syncthreads();
    #pragma unroll
    for (int i = 0; i < 32; i += 8)
        dst[((size_t)k * Cin + c0 + ty + i) * Hout + h0 + tx] = tile[ty + i][tx];
}

__global__ void transpose_deconvw_kernel(float* __restrict__ dst, const float* __restrict__ src)
{
    int idx = blockIdx.x * 256 + threadIdx.x;
    int o  = idx & 1023;
    int r  = idx >> 10;
    int ii = r & 1023;
    int ik = r >> 10;
    int i = ik / 3, k = ik - i * 3;
    dst[idx] = src[(size_t)i * 3 * HH + ((size_t)ii * 1024 + o) * 3 + k];
}

// ===================== 3xTF32 tensor-core GEMM =====================
// C(M,N) = A(M,K) @ B(K,N) [+bias][relu].  Tile 128x128x32, 256 threads,
// 8 warps (2 M x 4 N), per-warp 64x32 via 4x4 m16n8k8 mma, double-buffered
// cp.async.  A smem m-major stride 36, B smem k-major stride 136 (both
// conflict-free for the fragment access patterns).
#define ASZ 4608          // 128*36
#define BSZ 4352          // 32*136
#define STG 8960          // ASZ+BSZ
#define GEMM_SMEM (2*STG*4)

#define CP16(dst, src) asm volatile("cp.async.ca.shared.global [%0], [%1], 16;" :: "r"(dst), "l"(src))
#define CP16P(dst, src, sz) asm volatile("cp.async.ca.shared.global [%0], [%1], 16, %2;" :: "r"(dst), "l"(src), "r"(sz))
#define CP_COMMIT() asm volatile("cp.async.commit_group;")
#define CP_WAIT1() asm volatile("cp.async.wait_group 1;")
#define CP_WAIT0() asm volatile("cp.async.wait_group 0;")

__device__ __forceinline__ uint32_t f2tf(float x)
{
    uint32_t r;
    asm("cvt.rna.tf32.f32 %0, %1;" : "=r"(r) : "f"(x));
    return r;
}

#define MMA8(d, Ar, Br) \
    asm volatile("mma.sync.aligned.m16n8k8.row.col.f32.tf32.tf32.f32 " \
                 "{%0,%1,%2,%3},{%4,%5,%6,%7},{%8,%9},{%0,%1,%2,%3};" \
                 : "+f"((d)[0]), "+f"((d)[1]), "+f"((d)[2]), "+f"((d)[3]) \
                 : "r"((Ar)[0]), "r"((Ar)[1]), "r"((Ar)[2]), "r"((Ar)[3]), \
                   "r"((Br)[0]), "r"((Br)[1]))

__device__ __forceinline__ void compute_tile(const float* __restrict__ As,
                                             const float* __restrict__ Bs,
                                             float acc[4][4][4], int wm, int wn, int lane)
{
    const int lr = lane >> 2, lc = lane & 3;
    #pragma unroll
    for (int kk = 0; kk < 32; kk += 8) {
        uint32_t Ah[4][4], Al[4][4], Bh[4][2], Bl[4][2];
        #pragma unroll
        for (int mt = 0; mt < 4; mt++) {
            const float* ap = As + (wm * 64 + mt * 16 + lr) * 36 + kk + lc;
            float x0 = ap[0], x1 = ap[8 * 36], x2 = ap[4], x3 = ap[8 * 36 + 4];
            Ah[mt][0] = f2tf(x0); Al[mt][0] = f2tf(x0 - __uint_as_float(Ah[mt][0]));
            Ah[mt][1] = f2tf(x1); Al[mt][1] = f2tf(x1 - __uint_as_float(Ah[mt][1]));
            Ah[mt][2] = f2tf(x2); Al[mt][2] = f2tf(x2 - __uint_as_float(Ah[mt][2]));
            Ah[mt][3] = f2tf(x3); Al[mt][3] = f2tf(x3 - __uint_as_float(Ah[mt][3]));
        }
        #pragma unroll
        for (int nt = 0; nt < 4; nt++) {
            const float* bp = Bs + (kk + lc) * 136 + wn * 32 + nt * 8 + lr;
            float y0 = bp[0], y1 = bp[4 * 136];
            Bh[nt][0] = f2tf(y0); Bl[nt][0] = f2tf(y0 - __uint_as_float(Bh[nt][0]));
            Bh[nt][1] = f2tf(y1); Bl[nt][1] = f2tf(y1 - __uint_as_float(Bh[nt][1]));
        }
        #pragma unroll
        for (int mt = 0; mt < 4; mt++)
            #pragma unroll
            for (int nt = 0; nt < 4; nt++) {
                MMA8(acc[mt][nt], Ah[mt], Bh[nt]);
                MMA8(acc[mt][nt], Al[mt], Bh[nt]);
                MMA8(acc[mt][nt], Ah[mt], Bl[nt]);
            }
    }
}

__device__ __forceinline__ void gemm_epilogue(float acc[4][4][4], float* __restrict__ C,
                                              int N, int by, int bx, int wm, int wn,
                                              int lane, const float* __restrict__ bias,
                                              int relu)
{
    const int lr = lane >> 2, lc = (lane & 3) * 2;
    #pragma unroll
    for (int mt = 0; mt < 4; mt++) {
        int r0 = by * 128 + wm * 64 + mt * 16 + lr;
        #pragma unroll
        for (int nt = 0; nt < 4; nt++) {
            int c0 = bx * 128 + wn * 32 + nt * 8 + lc;
            float bx0 = 0.f, bx1 = 0.f;
            if (bias) { float2 bv = *(const float2*)(bias + c0); bx0 = bv.x; bx1 = bv.y; }
            float v0 = acc[mt][nt][0] + bx0, v1 = acc[mt][nt][1] + bx1;
            float v2 = acc[mt][nt][2] + bx0, v3 = acc[mt][nt][3] + bx1;
            if (relu) {
                v0 = fmaxf(v0, 0.f); v1 = fmaxf(v1, 0.f);
                v2 = fmaxf(v2, 0.f); v3 = fmaxf(v3, 0.f);
            }
            *(float2*)(C + (size_t)r0 * N + c0)       = make_float2(v0, v1);
            *(float2*)(C + (size_t)(r0 + 8) * N + c0) = make_float2(v2, v3);
        }
    }
}

__global__ __launch_bounds__(256) void gemm_tf32_kernel(
    const float* __restrict__ A, const float* __restrict__ B, float* __restrict__ C,
    int M, int N, int K, const float* __restrict__ bias, int relu)
{
    extern __shared__ float sm[];
    const int t = threadIdx.x;
    const int lane = t & 31, wid = t >> 5, wm = wid & 1, wn = wid >> 1;
    const int bx = blockIdx.x, by = blockIdx.y;
    const uint32_t smbase = (uint32_t)__cvta_generic_to_shared(sm);

    float acc[4][4][4];
    #pragma unroll
    for (int a = 0; a < 4; a++)
        #pragma unroll
        for (int b = 0; b < 4; b++)
            #pragma unroll
            for (int c = 0; c < 4; c++) acc[a][b][c] = 0.f;

    const int KT = K >> 5;
    auto load_tile = [&](int buf, int k0) {
        #pragma unroll
        for (int i = 0; i < 4; i++) {
            int idx = i * 256 + t;
            int m = idx >> 3, k4 = (idx & 7) << 2;
            const float* src = A + (size_t)(by * 128 + m) * K + k0 + k4;
            uint32_t dst = smbase + (uint32_t)(buf * STG + m * 36 + k4) * 4u;
            CP16(dst, src);
        }
        #pragma unroll
        for (int i = 0; i < 4; i++) {
            int idx = i * 256 + t;
            int kk = idx >> 5, n4 = (idx & 31) << 2;
            const float* src = B + (size_t)(k0 + kk) * N + bx * 128 + n4;
            uint32_t dst = smbase + (uint32_t)(buf * STG + ASZ + kk * 136 + n4) * 4u;
            CP16(dst, src);
        }
    };

    load_tile(0, 0);
    CP_COMMIT();
    for (int kt = 0; kt < KT; kt++) {
        if (kt + 1 < KT) {
            load_tile((kt + 1) & 1, (kt + 1) << 5);
            CP_COMMIT();
            CP_WAIT1();
        } else {
            CP_WAIT0();
        }
        __syncthreads();
        const float* base = sm + (kt & 1) * STG;
        compute_tile(base, base + ASZ, acc, wm, wn, lane);
        __syncthreads();
    }
    gemm_epilogue(acc, C, N, by, bx, wm, wn, lane, bias, relu);
}

// conv/deconv gather-A variant.
// mode 0 (conv k=3,p=1,s=1): tin = t + kseg - 1
// mode 1 (deconv k=3,p=1,op=s-1): tin = (t+1-kseg)/s when >=0 and divisible
__global__ __launch_bounds__(256) void convgemm_tf32_kernel(
    const float* __restrict__ In, const float* __restrict__ Wt, float* __restrict__ C,
    int Tout, int Tin, int Cin, int N, int stride, int mode,
    const float* __restrict__ bias, int relu)
{
    extern __shared__ float sm[];
    const int t = threadIdx.x;
    const int lane = t & 31, wid = t >> 5, wm = wid & 1, wn = wid >> 1;
    const int bx = blockIdx.x, by = blockIdx.y;
    const uint32_t smbase = (uint32_t)__cvta_generic_to_shared(sm);
    const int K = 3 * Cin;

    float acc[4][4][4];
    #pragma unroll
    for (int a = 0; a < 4; a++)
        #pragma unroll
        for (int b = 0; b < 4; b++)
            #pragma unroll
            for (int c = 0; c < 4; c++) acc[a][b][c] = 0.f;

    const int KT = K >> 5;
    auto load_tile = [&](int buf, int k0) {
        #pragma unroll
        for (int i = 0; i < 4; i++) {
            int idx = i * 256 + t;
            int m = idx >> 3, k4 = (idx & 7) << 2;
            int gr = by * 128 + m;
            int bb = gr / Tout, tt = gr - bb * Tout;
            int ka = k0 + k4;
            int kseg = ka / Cin, c = ka - kseg * Cin;
            const float* src = In;
            int sz = 0;
            if (mode == 0) {
                int tin = tt + kseg - 1;
                if (tin >= 0 && tin < Tin) {
                    src = In + ((size_t)(bb * Tin + tin) * Cin + c);
                    sz = 16;
                }
            } else {
                int num = tt + 1 - kseg;
                if (num >= 0 && (num % stride) == 0) {
                    int tin = num / stride;
                    if (tin < Tin) {
                        src = In + ((size_t)(bb * Tin + tin) * Cin + c);
                        sz = 16;
                    }
                }
            }
            uint32_t dst = smbase + (uint32_t)(buf * STG + m * 36 + k4) * 4u;
            CP16P(dst, src, sz);
        }
        #pragma unroll
        for (int i = 0; i < 4; i++) {
            int idx = i * 256 + t;
            int kk = idx >> 5, n4 = (idx & 31) << 2;
            const float* src = Wt + (size_t)(k0 + kk) * N + bx * 128 + n4;
            uint32_t dst = smbase + (uint32_t)(buf * STG + ASZ + kk * 136 + n4) * 4u;
            CP16(dst, src);
        }
    };

    load_tile(0, 0);
    CP_COMMIT();
    for (int kt = 0; kt < KT; kt++) {
        if (kt + 1 < KT) {
            load_tile((kt + 1) & 1, (kt + 1) << 5);
            CP_COMMIT();
            CP_WAIT1();
        } else {
            CP_WAIT0();
        }
        __syncthreads();
        const float* base = sm + (kt & 1) * STG;
        compute_tile(base, base + ASZ, acc, wm, wn, lane);
        __syncthreads();
    }
    gemm_epilogue(acc, C, N, by, bx, wm, wn, lane, bias, relu);
}

// ------------------------- fused attention (fp32, exact) --------------------
__global__ __launch_bounds__(128) void attn_kernel(
    const float* __restrict__ Q, const float* __restrict__ Kk, const float* __restrict__ V,
    float* __restrict__ O, int S, int windowed)
{
    extern __shared__ float smx[];
    float* Ks = smx;
    float* Vs = smx + 8192;
    float* Sc = smx + 16384;
    const int tid = threadIdx.x;
    const int qb = blockIdx.x, h = blockIdx.y, b = blockIdx.z;
    const int qi = qb * 128 + tid;
    const float* qp = Q + (((size_t)(b * S + qi)) * NHnum + h) * DHdim;
    float qv[64];
    #pragma unroll
    for (int d4 = 0; d4 < 16; d4++) {
        float4 v = *(const float4*)(qp + d4 * 4);
        qv[d4 * 4 + 0] = v.x; qv[d4 * 4 + 1] = v.y;
        qv[d4 * 4 + 2] = v.z; qv[d4 * 4 + 3] = v.w;
    }
    float acc[64];
    #pragma unroll
    for (int d = 0; d < 64; d++) acc[d] = 0.f;
    float mrow = -1e30f, lrow = 0.f;
    const int jb0 = windowed ? qb : 0;
    const int jb1 = windowed ? qb + 1 : (S >> 7);
    for (int jb = jb0; jb < jb1; jb++) {
        const float* kp = Kk + (((size_t)(b * S + jb * 128)) * NHnum + h) * DHdim;
        const float* vp = V  + (((size_t)(b * S + jb * 128)) * NHnum + h) * DHdim;
        #pragma unroll 4
        for (int i = tid; i < 2048; i += 128) {
            int r = i >> 4, c = i & 15;
            *(float4*)&Ks[r * 64 + c * 4] = *(const float4*)(kp + (size_t)r * Hdim + c * 4);
            *(float4*)&Vs[r * 64 + c * 4] = *(const float4*)(vp + (size_t)r * Hdim + c * 4);
        }
        __syncthreads();
        float bmax = -1e30f;
        for (int j = 0; j < 128; j++) {
            const float4* kr = (const float4*)(Ks + j * 64);
            float s0 = 0.f, s1 = 0.f, s2 = 0.f, s3 = 0.f;
            #pragma unroll
            for (int d4 = 0; d4 < 16; d4++) {
                float4 kv = kr[d4];
                s0 += qv[d4 * 4 + 0] * kv.x; s1 += qv[d4 * 4 + 1] * kv.y;
                s2 += qv[d4 * 4 + 2] * kv.z; s3 += qv[d4 * 4 + 3] * kv.w;
            }
            float sres = ((s0 + s1) + (s2 + s3)) * 0.125f;
            Sc[j * 128 + tid] = sres;
            bmax = fmaxf(bmax, sres);
        }
        float nm = fmaxf(mrow, bmax);
        float corr = __expf(mrow - nm);
        lrow *= corr;
        #pragma unroll
        for (int d = 0; d < 64; d++) acc[d] *= corr;
        for (int j = 0; j < 128; j++) {
            float p = __expf(Sc[j * 128 + tid] - nm);
            lrow += p;
            const float4* vr = (const float4*)(Vs + j * 64);
            #pragma unroll
            for (int d4 = 0; d4 < 16; d4++) {
                float4 vv = vr[d4];
                acc[d4 * 4 + 0] += p * vv.x; acc[d4 * 4 + 1] += p * vv.y;
                acc[d4 * 4 + 2] += p * vv.z; acc[d4 * 4 + 3] += p * vv.w;
            }
        }
        mrow = nm;
        __syncthreads();
    }
    const float invl = 1.f / lrow;
    float* op = O + (((size_t)(b * S + qi)) * NHnum + h) * DHdim;
    #pragma unroll
    for (int d4 = 0; d4 < 16; d4++)
        *(float4*)(op + d4 * 4) = make_float4(acc[d4 * 4 + 0] * invl, acc[d4 * 4 + 1] * invl,
                                              acc[d4 * 4 + 2] * invl, acc[d4 * 4 + 3] * invl);
}

// ------------------------- LayerNorm(in1 + in2) ------------------------------
__global__ __launch_bounds__(256) void ln_kernel(
    float* __restrict__ out, const float* __restrict__ in1, const float* __restrict__ in2,
    const float* __restrict__ g, const float* __restrict__ be)
{
    __shared__ float rs[8], rss[8];
    const int row = blockIdx.x, tid = threadIdx.x;
    const size_t base = (size_t)row * Hdim + tid * 4;
    float4 a = *(const float4*)(in1 + base);
    float4 b2 = *(const float4*)(in2 + base);
    a.x += b2.x; a.y += b2.y; a.z += b2.z; a.w += b2.w;
    float s  = a.x + a.y + a.z + a.w;
    float ss = a.x * a.x + a.y * a.y + a.z * a.z + a.w * a.w;
    #pragma unroll
    for (int o = 16; o > 0; o >>= 1) {
        s  += __shfl_xor_sync(0xffffffffu, s, o);
        ss += __shfl_xor_sync(0xffffffffu, ss, o);
    }
    if ((tid & 31) == 0) { rs[tid >> 5] = s; rss[tid >> 5] = ss; }
    __syncthreads();
    float st = 0.f, sst = 0.f;
    #pragma unroll
    for (int i = 0; i < 8; i++) { st += rs[i]; sst += rss[i]; }
    const float mean = st * (1.f / 1024.f);
    const float var  = sst * (1.f / 1024.f) - mean * mean;
    const float inv  = rsqrtf(var + 1e-5f);
    float4 gg = *(const float4*)(g + tid * 4);
    float4 bb = *(const float4*)(be + tid * 4);
    float4 o4;
    o4.x = (a.x - mean) * inv * gg.x + bb.x;
    o4.y = (a.y - mean) * inv * gg.y + bb.y;
    o4.z = (a.z - mean) * inv * gg.z + bb.z;
    o4.w = (a.w - mean) * inv * gg.w + bb.w;
    *(float4*)(out + base) = o4;
}

// ------------------------- pool / add ---------------------------------------
__global__ void poolrelu_kernel(float* __restrict__ out, const float* __restrict__ in,
                                int S2, int n4)
{
    int idx = blockIdx.x * blockDim.x + threadIdx.x;
    if (idx >= n4) return;
    int h4 = idx & 255;
    int bt = idx >> 8;
    int b = bt / S2, t2 = bt - b * S2;
    const float4* i0 = (const float4*)in + ((size_t)(b * S2 * 2 + t2 * 2) * 256 + h4);
    float4 a = i0[0], c = i0[256];
    float4 o;
    o.x = fmaxf(fmaxf(a.x, c.x), 0.f);
    o.y = fmaxf(fmaxf(a.y, c.y), 0.f);
    o.z = fmaxf(fmaxf(a.z, c.z), 0.f);
    o.w = fmaxf(fmaxf(a.w, c.w), 0.f);
    ((float4*)out)[idx] = o;
}

__global__ void add_kernel(float* __restrict__ out, const float* __restrict__ a,
                           const float* __restrict__ b, int n4)
{
    int i = blockIdx.x * blockDim.x + threadIdx.x;
    if (i >= n4) return;
    float4 x = ((const float4*)a)[i], y = ((const float4*)b)[i];
    ((float4*)out)[i] = make_float4(x.x + y.x, x.y + y.y, x.z + y.z, x.w + y.w);
}

// ------------------------- host orchestration -------------------------------
static inline void sgemm(const float* A, const float* B, float* C, int M, int N, int K,
                         const float* bias, int relu)
{
    dim3 g(N / 128, M / 128);
    gemm_tf32_kernel<<<g, 256, GEMM_SMEM>>>(A, B, C, M, N, K, bias, relu);
}

extern "C" void kernel_launch(void* const* d_in, const int* in_sizes, int n_in,
                              void* d_out, int out_size)
{
    (void)in_sizes; (void)n_in; (void)out_size;
    const float* x          = (const float*)d_in[0];
    const float* emb_w      = (const float*)d_in[1];
    const float* emb_b      = (const float*)d_in[2];
    const float* enc_qkvo   = (const float*)d_in[3];
    const float* enc_ln     = (const float*)d_in[4];
    const float* enc_ffn_w1 = (const float*)d_in[5];
    const float* enc_ffn_b1 = (const float*)d_in[6];
    const float* enc_ffn_w2 = (const float*)d_in[7];
    const float* enc_ffn_b2 = (const float*)d_in[8];
    const float* conv0_w    = (const float*)d_in[9];
    const float* conv0_b    = (const float*)d_in[10];
    const float* dec_qkvo0  = (const float*)d_in[11];
    const float* dec_ln0    = (const float*)d_in[12];
    const float* dec_attn1  = (const float*)d_in[13];
    const float* dec_attn2  = (const float*)d_in[14];
    const float* dec_ln     = (const float*)d_in[15];
    const float* dec_ffn_w1 = (const float*)d_in[16];
    const float* dec_ffn_b1 = (const float*)d_in[17];
    const float* dec_ffn_w2 = (const float*)d_in[18];
    const float* dec_ffn_b2 = (const float*)d_in[19];
    const float* dec_dw     = (const float*)d_in[20];
    const float* dec_db     = (const float*)d_in[21];

    float *xT, *wTe, *wTc, *wTd, *bX, *bQ, *bK, *bV, *bA, *bT, *bY, *bD, *bY2, *bZ, *bF;
    cudaGetSymbolAddress((void**)&xT,  g_xT);
    cudaGetSymbolAddress((void**)&wTe, g_wTe);
    cudaGetSymbolAddress((void**)&wTc, g_wTc);
    cudaGetSymbolAddress((void**)&wTd, g_wTd);
    cudaGetSymbolAddress((void**)&bX,  g_bufX);
    cudaGetSymbolAddress((void**)&bQ,  g_bufQ);
    cudaGetSymbolAddress((void**)&bK,  g_bufK);
    cudaGetSymbolAddress((void**)&bV,  g_bufV);
    cudaGetSymbolAddress((void**)&bA,  g_bufA);
    cudaGetSymbolAddress((void**)&bT,  g_bufT);
    cudaGetSymbolAddress((void**)&bY,  g_bufY);
    cudaGetSymbolAddress((void**)&bD,  g_bufD);
    cudaGetSymbolAddress((void**)&bY2, g_bufY2);
    cudaGetSymbolAddress((void**)&bZ,  g_bufZ);
    cudaGetSymbolAddress((void**)&bF,  g_bufF);

    float* out = (float*)d_out;
    float* Z0  = out;
    float* Z1  = out + (size_t)4194304;
    float* Z2  = out + (size_t)8388608;
    float* Z3  = out + (size_t)10485760;
    float* FD0 = out + (size_t)11534336;
    float* FD1 = out + (size_t)12582912;
    float* FD2 = out + (size_t)14680064;
    float* FD3 = out + (size_t)18874368;

    cudaFuncSetAttribute(attn_kernel, cudaFuncAttributeMaxDynamicSharedMemorySize, 131072);
    cudaFuncSetAttribute(gemm_tf32_kernel, cudaFuncAttributeMaxDynamicSharedMemorySize, GEMM_SMEM);
    cudaFuncSetAttribute(convgemm_tf32_kernel, cudaFuncAttributeMaxDynamicSharedMemorySize, GEMM_SMEM);

    // ---- transposes ----
    {
        dim3 blk(32, 8);
        transpose2d_kernel    <<<dim3(Tfull/32, DINc/32, Bb), blk>>>(xT, x, DINc, Tfull);
        transpose_convw_kernel<<<dim3(DINc/32, Hdim/32, 3),   blk>>>(wTe, emb_w, Hdim, DINc);
        transpose_convw_kernel<<<dim3(Hdim/32, Hdim/32, 3),   blk>>>(wTc, conv0_w, Hdim, Hdim);
        transpose_deconvw_kernel<<<(3*3*HH)/256, 256>>>(wTd, dec_dw);
    }

    // ---- embedding conv + relu: (B,T,DIN) -> bX (B,T,H) ----
    convgemm_tf32_kernel<<<dim3(Hdim/128, (Bb*Tfull)/128), 256, GEMM_SMEM>>>(
        xT, wTe, bX, Tfull, Tfull, DINc, Hdim, 1, 0, emb_b, 1);

    auto mha = [&](const float* xq, const float* xkv, const float* w, int S, int windowed) {
        int rows = Bb * S;
        sgemm(xq,  w + 0*(size_t)HH, bQ, rows, Hdim, Hdim, nullptr, 0);
        sgemm(xkv, w + 1*(size_t)HH, bK, rows, Hdim, Hdim, nullptr, 0);
        sgemm(xkv, w + 2*(size_t)HH, bV, rows, Hdim, Hdim, nullptr, 0);
        attn_kernel<<<dim3(S/128, NHnum, Bb), 128, 131072>>>(bQ, bK, bV, bA, S, windowed);
        sgemm(bA, w + 3*(size_t)HH, bT, rows, Hdim, Hdim, nullptr, 0);
    };

    // ================= encoder =================
    const int encS[4] = {1024, 1024, 512, 256};
    float* Zp[4] = {Z0, Z1, Z2, Z3};
    for (int i = 0; i < 4; i++) {
        int S = encS[i], rows = Bb * S;
        const float* w = enc_qkvo + (size_t)i * 4 * HH;
        mha(bX, bX, w, S, 1);
        const float* lnb = enc_ln + (size_t)i * 4 * Hdim;
        ln_kernel<<<rows, 256>>>(bY, bX, bT, lnb + 0*Hdim, lnb + 1*Hdim);
        sgemm(bY, enc_ffn_w1 + (size_t)i*Hdim*Ff, bF, rows, Ff, Hdim,
              enc_ffn_b1 + (size_t)i*Ff, 1);
        sgemm(bF, enc_ffn_w2 + (size_t)i*Ff*Hdim, bT, rows, Hdim, Ff,
              enc_ffn_b2 + (size_t)i*Hdim, 0);
        ln_kernel<<<rows, 256>>>(Zp[i], bY, bT, lnb + 2*Hdim, lnb + 3*Hdim);
        if (i == 0) {
            convgemm_tf32_kernel<<<dim3(Hdim/128, rows/128), 256, GEMM_SMEM>>>(
                Zp[i], wTc, bX, S, S, Hdim, Hdim, 1, 0, conv0_b, 1);
        } else if (i < 3) {
            int S2 = S / 2, n4 = Bb * S2 * (Hdim/4);
            poolrelu_kernel<<<(n4 + 255)/256, 256>>>(bX, Zp[i], S2, n4);
        }
    }

    // ================= decoder level 0 =================
    {
        int S = 256, rows = Bb * S;
        mha(Z3, Z3, dec_qkvo0, S, 0);
        ln_kernel<<<rows, 256>>>(FD0, Z3, bT, dec_ln0, dec_ln0 + Hdim);
    }

    // ================= decoder levels =================
    const float* fdPrev = FD0; int Sprev = 256;
    const float* feP[3] = {Z2, Z1, Z0};
    const int    decS[3] = {512, 1024, 1024};
    const int    decStride[3] = {2, 2, 1};
    float* fdOut[3] = {FD1, FD2, FD3};
    for (int i = 0; i < 3; i++) {
        int S = decS[i], rows = Bb * S, st = decStride[i];
        convgemm_tf32_kernel<<<dim3(Hdim/128, rows/128), 256, GEMM_SMEM>>>(
            fdPrev, wTd + (size_t)i*3*HH, bD, S, Sprev, Hdim, Hdim, st, 1,
            dec_db + (size_t)i*Hdim, 1);
        const float* a1 = dec_attn1 + (size_t)i * 4 * HH;
        const float* a2 = dec_attn2 + (size_t)i * 4 * HH;
        const float* lnb = dec_ln + (size_t)i * 6 * Hdim;
        mha(feP[i], bD, a1, S, 0);
        ln_kernel<<<rows, 256>>>(bY, feP[i], bT, lnb + 0*Hdim, lnb + 1*Hdim);
        mha(bD, feP[i], a2, S, 0);
        ln_kernel<<<rows, 256>>>(bY2, bD, bT, lnb + 2*Hdim, lnb + 3*Hdim);
        int n4 = rows * (Hdim/4);
        add_kernel<<<(n4 + 255)/256, 256>>>(bZ, bY, bY2, n4);
        sgemm(bZ, dec_ffn_w1 + (size_t)i*Hdim*Ff, bF, rows, Ff, Hdim,
              dec_ffn_b1 + (size_t)i*Ff, 1);
        sgemm(bF, dec_ffn_w2 + (size_t)i*Ff*Hdim, bT, rows, Hdim, Ff,
              dec_ffn_b2 + (size_t)i*Hdim, 0);
        ln_kernel<<<rows, 256>>>(fdOut[i], bZ, bT, lnb + 4*Hdim, lnb + 5*Hdim);
        fdPrev = fdOut[i]; Sprev = S;
    }
}

// round 7
// speedup vs baseline: 1.3582x; 1.3582x over previous
#include <cuda_runtime.h>
#include <cuda_fp16.h>
#include <cstdint>
#include <cstddef>

#define HH (1024*1024)
#define NHnum 16
#define DHdim 64
#define WTOT ((size_t)124518400)
#define IMLO ((size_t)28311552)
#define ASLO ((size_t)16777216)

__device__ __half g_W [(size_t)2*WTOT];
__device__ __half g_im[(size_t)2*28311552];
__device__ __half g_As[(size_t)2*16777216];
__device__ float  g_xT[(size_t)9437184];
__device__ float  g_buf[(size_t)56*HH];

__device__ __forceinline__ void sp2(float a, float b, __half2* hi, __half2* lo)
{
    __half2 h = __floats2half2_rn(a, b);
    float2 f = __half22float2(h);
    *hi = h;
    *lo = __floats2half2_rn(a - f.x, b - f.y);
}

// ---------------- prep kernels ----------------
__global__ void transpose2d_kernel(float* dst, const float* src, int R, int C)
{
    __shared__ float tile[32][33];
    int b = blockIdx.z;
    const float* s = src + (size_t)b * R * C;
    float* d = dst + (size_t)b * R * C;
    int c0 = blockIdx.x * 32, r0 = blockIdx.y * 32, tx = threadIdx.x, ty = threadIdx.y;
    for (int i = 0; i < 32; i += 8) tile[ty + i][tx] = s[(size_t)(r0 + ty + i) * C + c0 + tx];
    __syncthreads();
    for (int i = 0; i < 32; i += 8) d[(size_t)(c0 + ty + i) * R + r0 + tx] = tile[tx][ty + i];
}

// weight (K,N) -> fp16 planes (N,K), z-batched
__global__ void wsplit_kernel(__half* hi, __half* lo, const float* src, int K, int N)
{
    __shared__ float tile[32][33];
    size_t mo = (size_t)blockIdx.z * K * N;
    int n0 = blockIdx.x * 32, k0 = blockIdx.y * 32, tx = threadIdx.x, ty = threadIdx.y;
    for (int i = 0; i < 32; i += 8) tile[ty + i][tx] = src[mo + (size_t)(k0 + ty + i) * N + n0 + tx];
    __syncthreads();
    for (int i = 0; i < 32; i += 8) {
        float x = tile[tx][ty + i];
        __half h = __float2half_rn(x);
        size_t o = mo + (size_t)(n0 + ty + i) * K + k0 + tx;
        hi[o] = h; lo[o] = __float2half_rn(x - __half2float(h));
    }
}

// conv weight (Hout,Cin,3) -> planes (Hout, 3*Cin)
__global__ void convw_split_kernel(__half* hi, __half* lo, const float* src, int Cin, int total)
{
    int idx = blockIdx.x * 256 + threadIdx.x;
    if (idx >= total) return;
    int K = 3 * Cin;
    int n = idx / K, r = idx - n * K;
    int ks = r / Cin, c = r - ks * Cin;
    float x = src[((size_t)n * Cin + c) * 3 + ks];
    __half h = __float2half_rn(x);
    hi[idx] = h; lo[idx] = __float2half_rn(x - __half2float(h));
}

// deconv weight (3,Hin,Hout,3) -> 3 x planes (Hout, 3*Hin); flip/IO folded
__global__ void deconvw_split_kernel(__half* hi, __half* lo, const float* src)
{
    int idx = blockIdx.x * 256 + threadIdx.x;
    int i = blockIdx.y;
    int o = idx / 3072, r = idx - o * 3072;
    int ks = r >> 10, c = r & 1023;
    float x = src[(size_t)i * 3 * HH + ((size_t)c * 1024 + o) * 3 + ks];
    __half h = __float2half_rn(x);
    size_t d = (size_t)i * 3 * HH + idx;
    hi[d] = h; lo[d] = __float2half_rn(x - __half2float(h));
}

__global__ void split_kernel(__half* hi, __half* lo, const float* src, int n4)
{
    int i = blockIdx.x * 256 + threadIdx.x;
    if (i >= n4) return;
    float4 v = ((const float4*)src)[i];
    __half2 h01, l01, h23, l23;
    sp2(v.x, v.y, &h01, &l01);
    sp2(v.z, v.w, &h23, &l23);
    *(__half2*)(hi + 4*(size_t)i)     = h01;
    *(__half2*)(hi + 4*(size_t)i + 2) = h23;
    *(__half2*)(lo + 4*(size_t)i)     = l01;
    *(__half2*)(lo + 4*(size_t)i + 2) = l23;
}

// im2col planes: In (B,Tin,Cin) fp32 -> (B*Tout, 3*Cin) fp16 planes
__global__ void im2col_split_kernel(__half* hi, __half* lo, const float* In,
                                    int Tout, int Tin, int Cin, int stride, int mode, int total4)
{
    int idx = blockIdx.x * 256 + threadIdx.x;
    if (idx >= total4) return;
    int kw = 3 * Cin / 4, cq4 = Cin / 4;
    int kq = idx % kw, m = idx / kw;
    int ks = kq / cq4, c4 = kq - ks * cq4;
    int b = m / Tout, tt = m - b * Tout;
    float4 v = make_float4(0.f, 0.f, 0.f, 0.f);
    int tin = -1;
    if (mode == 0) { int ti = tt + ks - 1; if (ti >= 0 && ti < Tin) tin = ti; }
    else { int num = tt + 1 - ks;
           if (num >= 0 && num % stride == 0) { int ti = num / stride; if (ti < Tin) tin = ti; } }
    if (tin >= 0) v = *(const float4*)(In + ((size_t)(b * Tin + tin) * Cin + c4 * 4));
    __half2 h01, l01, h23, l23;
    sp2(v.x, v.y, &h01, &l01);
    sp2(v.z, v.w, &h23, &l23);
    *(__half2*)(hi + 4*(size_t)idx)     = h01;
    *(__half2*)(hi + 4*(size_t)idx + 2) = h23;
    *(__half2*)(lo + 4*(size_t)idx)     = l01;
    *(__half2*)(lo + 4*(size_t)idx + 2) = l23;
}

// ---------------- fp16x2-split tensor GEMM ----------------
// C(M,N) = A(M,K) @ B(N,K)^T + bias [relu].  Tile 128x128x32, 256 thr,
// 8 warps (2M x 4N), warp 64x32, mma.m16n8k16.f16.f32, terms hh+lh+hl.
// smem: per stage A hi|lo then B hi|lo, 128 rows x 80B pitch (conflict-free).
#define GEMM_SM 81920
#define CP16(d, s) asm volatile("cp.async.ca.shared.global [%0], [%1], 16;" :: "r"(d), "l"(s))
#define LDSM4(r, a) asm volatile( \
    "ldmatrix.sync.aligned.m8n8.x4.shared.b16 {%0,%1,%2,%3}, [%4];" \
    : "=r"((r)[0]), "=r"((r)[1]), "=r"((r)[2]), "=r"((r)[3]) : "r"(a))
#define MMA16(d, A_, B_) asm volatile( \
    "mma.sync.aligned.m16n8k16.row.col.f32.f16.f16.f32 " \
    "{%0,%1,%2,%3},{%4,%5,%6,%7},{%8,%9},{%0,%1,%2,%3};" \
    : "+f"((d)[0]), "+f"((d)[1]), "+f"((d)[2]), "+f"((d)[3]) \
    : "r"((A_)[0]), "r"((A_)[1]), "r"((A_)[2]), "r"((A_)[3]), "r"((B_)[0]), "r"((B_)[1]))

__global__ __launch_bounds__(256) void gemm_fp16(
    const __half* Ah, const __half* Al, const __half* Bh, const __half* Bl,
    float* C, int M, int N, int K, const float* bias, int relu)
{
    extern __shared__ char smc[];
    const uint32_t smb = (uint32_t)__cvta_generic_to_shared(smc);
    const int t = threadIdx.x, lane = t & 31, wid = t >> 5;
    const int wm = wid & 1, wn = wid >> 1;
    const int bx = blockIdx.x, by = blockIdx.y;

    float acc[4][4][4];
    #pragma unroll
    for (int a = 0; a < 4; a++)
        #pragma unroll
        for (int b = 0; b < 4; b++)
            #pragma unroll
            for (int c = 0; c < 4; c++) acc[a][b][c] = 0.f;

    const __half* P[4] = {Ah, Al, Bh, Bl};
    const int KT = K >> 5;

    auto LD = [&](int s, int k0) {
        uint32_t sb = smb + (uint32_t)s * 40960u;
        #pragma unroll
        for (int p = 0; p < 4; p++) {
            const __half* src = P[p] + (size_t)((p < 2 ? by : bx) * 128) * K + k0;
            #pragma unroll
            for (int i = 0; i < 2; i++) {
                int idx = i * 256 + t, r = idx >> 2, c = idx & 3;
                CP16(sb + (uint32_t)p * 10240u + (uint32_t)(r * 80 + c * 16),
                     src + (size_t)r * K + c * 8);
            }
        }
    };

    auto COMP = [&](int s) {
        uint32_t sb = smb + (uint32_t)s * 40960u;
        const int arow = wm * 64 + (lane & 7) + ((lane >> 3) & 1) * 8;
        const int brow = wn * 32 + (lane & 7) + ((lane >> 4) & 1) * 8;
        #pragma unroll
        for (int kk = 0; kk < 2; kk++) {
            uint32_t ah[4][4], al[4][4], bh[4][2], bl[4][2];
            const int achk = kk * 2 + (lane >> 4);
            const int bchk = kk * 2 + ((lane >> 3) & 1);
            #pragma unroll
            for (int mt = 0; mt < 4; mt++) {
                uint32_t ad = sb + (uint32_t)((arow + mt * 16) * 80 + achk * 16);
                LDSM4(ah[mt], ad);
                LDSM4(al[mt], ad + 10240u);
            }
            #pragma unroll
            for (int np = 0; np < 2; np++) {
                uint32_t bd = sb + 20480u + (uint32_t)((brow + np * 16) * 80 + bchk * 16);
                uint32_t r4[4];
                LDSM4(r4, bd);
                bh[np*2][0] = r4[0]; bh[np*2][1] = r4[1];
                bh[np*2+1][0] = r4[2]; bh[np*2+1][1] = r4[3];
                LDSM4(r4, bd + 10240u);
                bl[np*2][0] = r4[0]; bl[np*2][1] = r4[1];
                bl[np*2+1][0] = r4[2]; bl[np*2+1][1] = r4[3];
            }
            #pragma unroll
            for (int mt = 0; mt < 4; mt++)
                #pragma unroll
                for (int nt = 0; nt < 4; nt++) {
                    MMA16(acc[mt][nt], ah[mt], bh[nt]);
                    MMA16(acc[mt][nt], al[mt], bh[nt]);
                    MMA16(acc[mt][nt], ah[mt], bl[nt]);
                }
        }
    };

    LD(0, 0);
    asm volatile("cp.async.commit_group;");
    for (int kt = 0; kt < KT; kt++) {
        if (kt + 1 < KT) {
            LD((kt + 1) & 1, (kt + 1) << 5);
            asm volatile("cp.async.commit_group;");
            asm volatile("cp.async.wait_group 1;");
        } else {
            asm volatile("cp.async.wait_group 0;");
        }
        __syncthreads();
        COMP(kt & 1);
        __syncthreads();
    }

    const int lr = lane >> 2, lc = (lane & 3) * 2;
    #pragma unroll
    for (int mt = 0; mt < 4; mt++) {
        int r0 = by * 128 + wm * 64 + mt * 16 + lr;
        #pragma unroll
        for (int nt = 0; nt < 4; nt++) {
            int c0 = bx * 128 + wn * 32 + nt * 8 + lc;
            float b0 = 0.f, b1 = 0.f;
            if (bias) { float2 bv = *(const float2*)(bias + c0); b0 = bv.x; b1 = bv.y; }
            float v0 = acc[mt][nt][0] + b0, v1 = acc[mt][nt][1] + b1;
            float v2 = acc[mt][nt][2] + b0, v3 = acc[mt][nt][3] + b1;
            if (relu) { v0 = fmaxf(v0,0.f); v1 = fmaxf(v1,0.f);
                        v2 = fmaxf(v2,0.f); v3 = fmaxf(v3,0.f); }
            *(float2*)(C + (size_t)r0 * N + c0)       = make_float2(v0, v1);
            *(float2*)(C + (size_t)(r0 + 8) * N + c0) = make_float2(v2, v3);
        }
    }
}

// ---------------- attention / ln / pool / add (fp32) ----------------
__global__ __launch_bounds__(128) void attn_kernel(
    const float* Q, const float* Kk, const float* V, float* O, int S, int windowed)
{
    extern __shared__ float smx[];
    float* Ks = smx; float* Vs = smx + 8192; float* Sc = smx + 16384;
    const int tid = threadIdx.x, qb = blockIdx.x, h = blockIdx.y, b = blockIdx.z;
    const int qi = qb * 128 + tid;
    const float* qp = Q + (((size_t)(b * S + qi)) * NHnum + h) * DHdim;
    float qv[64], acc[64];
    for (int d4 = 0; d4 < 16; d4++) {
        float4 v = *(const float4*)(qp + d4 * 4);
        qv[d4*4] = v.x; qv[d4*4+1] = v.y; qv[d4*4+2] = v.z; qv[d4*4+3] = v.w;
    }
    for (int d = 0; d < 64; d++) acc[d] = 0.f;
    float mrow = -1e30f, lrow = 0.f;
    const int jb0 = windowed ? qb : 0, jb1 = windowed ? qb + 1 : (S >> 7);
    for (int jb = jb0; jb < jb1; jb++) {
        const float* kp = Kk + (((size_t)(b * S + jb * 128)) * NHnum + h) * DHdim;
        const float* vp = V  + (((size_t)(b * S + jb * 128)) * NHnum + h) * DHdim;
        for (int i = tid; i < 2048; i += 128) {
            int r = i >> 4, c = i & 15;
            *(float4*)&Ks[r*64 + c*4] = *(const float4*)(kp + (size_t)r * 1024 + c*4);
            *(float4*)&Vs[r*64 + c*4] = *(const float4*)(vp + (size_t)r * 1024 + c*4);
        }
        __syncthreads();
        float bmax = -1e30f;
        for (int j = 0; j < 128; j++) {
            const float4* kr = (const float4*)(Ks + j * 64);
            float s0 = 0.f, s1 = 0.f, s2 = 0.f, s3 = 0.f;
            for (int d4 = 0; d4 < 16; d4++) {
                float4 kv = kr[d4];
                s0 += qv[d4*4]*kv.x; s1 += qv[d4*4+1]*kv.y;
                s2 += qv[d4*4+2]*kv.z; s3 += qv[d4*4+3]*kv.w;
            }
            float sr = ((s0+s1)+(s2+s3)) * 0.125f;
            Sc[j*128 + tid] = sr; bmax = fmaxf(bmax, sr);
        }
        float nm = fmaxf(mrow, bmax), corr = __expf(mrow - nm);
        lrow *= corr;
        for (int d = 0; d < 64; d++) acc[d] *= corr;
        for (int j = 0; j < 128; j++) {
            float p = __expf(Sc[j*128 + tid] - nm);
            lrow += p;
            const float4* vr = (const float4*)(Vs + j * 64);
            for (int d4 = 0; d4 < 16; d4++) {
                float4 vv = vr[d4];
                acc[d4*4] += p*vv.x; acc[d4*4+1] += p*vv.y;
                acc[d4*4+2] += p*vv.z; acc[d4*4+3] += p*vv.w;
            }
        }
        mrow = nm;
        __syncthreads();
    }
    const float invl = 1.f / lrow;
    float* op = O + (((size_t)(b * S + qi)) * NHnum + h) * DHdim;
    for (int d4 = 0; d4 < 16; d4++)
        *(float4*)(op + d4*4) = make_float4(acc[d4*4]*invl, acc[d4*4+1]*invl,
                                            acc[d4*4+2]*invl, acc[d4*4+3]*invl);
}

__global__ __launch_bounds__(256) void ln_kernel(
    float* out, const float* in1, const float* in2, const float* g, const float* be)
{
    __shared__ float rs[8], rss[8];
    const int row = blockIdx.x, tid = threadIdx.x;
    const size_t base = (size_t)row * 1024 + tid * 4;
    float4 a = *(const float4*)(in1 + base), b2 = *(const float4*)(in2 + base);
    a.x += b2.x; a.y += b2.y; a.z += b2.z; a.w += b2.w;
    float s = a.x + a.y + a.z + a.w;
    float ss = a.x*a.x + a.y*a.y + a.z*a.z + a.w*a.w;
    for (int o = 16; o > 0; o >>= 1) {
        s += __shfl_xor_sync(0xffffffffu, s, o);
        ss += __shfl_xor_sync(0xffffffffu, ss, o);
    }
    if ((tid & 31) == 0) { rs[tid >> 5] = s; rss[tid >> 5] = ss; }
    __syncthreads();
    float st = 0.f, sst = 0.f;
    for (int i = 0; i < 8; i++) { st += rs[i]; sst += rss[i]; }
    const float mean = st * (1.f/1024.f), var = sst * (1.f/1024.f) - mean*mean;
    const float inv = rsqrtf(var + 1e-5f);
    float4 gg = *(const float4*)(g + tid*4), bb = *(const float4*)(be + tid*4), o4;
    o4.x = (a.x-mean)*inv*gg.x + bb.x; o4.y = (a.y-mean)*inv*gg.y + bb.y;
    o4.z = (a.z-mean)*inv*gg.z + bb.z; o4.w = (a.w-mean)*inv*gg.w + bb.w;
    *(float4*)(out + base) = o4;
}

__global__ void poolrelu_kernel(float* out, const float* in, int S2, int n4)
{
    int idx = blockIdx.x * blockDim.x + threadIdx.x;
    if (idx >= n4) return;
    int h4 = idx & 255, bt = idx >> 8, b = bt / S2, t2 = bt - b * S2;
    const float4* i0 = (const float4*)in + ((size_t)(b*S2*2 + t2*2) * 256 + h4);
    float4 a = i0[0], c = i0[256], o;
    o.x = fmaxf(fmaxf(a.x,c.x),0.f); o.y = fmaxf(fmaxf(a.y,c.y),0.f);
    o.z = fmaxf(fmaxf(a.z,c.z),0.f); o.w = fmaxf(fmaxf(a.w,c.w),0.f);
    ((float4*)out)[idx] = o;
}

__global__ void add_kernel(float* out, const float* a, const float* b, int n4)
{
    int i = blockIdx.x * blockDim.x + threadIdx.x;
    if (i >= n4) return;
    float4 x = ((const float4*)a)[i], y = ((const float4*)b)[i];
    ((float4*)out)[i] = make_float4(x.x+y.x, x.y+y.y, x.z+y.z, x.w+y.w);
}

// ---------------- host ----------------
extern "C" void kernel_launch(void* const* d_in, const int* in_sizes, int n_in,
                              void* d_out, int out_size)
{
    (void)in_sizes; (void)n_in; (void)out_size;
    const float* x        = (const float*)d_in[0];
    const float* emb_w    = (const float*)d_in[1];
    const float* emb_b    = (const float*)d_in[2];
    const float* enc_qkvo = (const float*)d_in[3];
    const float* enc_ln   = (const float*)d_in[4];
    const float* ef1      = (const float*)d_in[5];
    const float* eb1      = (const float*)d_in[6];
    const float* ef2      = (const float*)d_in[7];
    const float* eb2      = (const float*)d_in[8];
    const float* conv0_w  = (const float*)d_in[9];
    const float* conv0_b  = (const float*)d_in[10];
    const float* dq0      = (const float*)d_in[11];
    const float* dln0     = (const float*)d_in[12];
    const float* da1      = (const float*)d_in[13];
    const float* da2      = (const float*)d_in[14];
    const float* dln      = (const float*)d_in[15];
    const float* df1      = (const float*)d_in[16];
    const float* db1      = (const float*)d_in[17];
    const float* df2      = (const float*)d_in[18];
    const float* db2      = (const float*)d_in[19];
    const float* ddw      = (const float*)d_in[20];
    const float* ddb      = (const float*)d_in[21];

    __half *W, *im, *As;
    float *xT, *buf;
    cudaGetSymbolAddress((void**)&W,  g_W);
    cudaGetSymbolAddress((void**)&im, g_im);
    cudaGetSymbolAddress((void**)&As, g_As);
    cudaGetSymbolAddress((void**)&xT, g_xT);
    cudaGetSymbolAddress((void**)&buf, g_buf);

    float *bX = buf, *bQ = buf+(size_t)4*HH, *bK = buf+(size_t)8*HH, *bV = buf+(size_t)12*HH,
          *bA = buf+(size_t)16*HH, *bT = buf+(size_t)20*HH, *bY = buf+(size_t)24*HH,
          *bD = buf+(size_t)28*HH, *bY2 = buf+(size_t)32*HH, *bZ = buf+(size_t)36*HH,
          *bF = buf+(size_t)40*HH;
    __half *AsL = As + ASLO, *imL = im + IMLO;

    const size_t oE = 0, oD0 = (size_t)16*HH, oD1 = (size_t)20*HH, oD2 = (size_t)32*HH,
                 oF1e = (size_t)44*HH, oF2e = (size_t)60*HH, oF1d = (size_t)76*HH,
                 oF2d = (size_t)88*HH, oWe = (size_t)100*HH,
                 oWc = oWe + 7077888, oWd = oWc + (size_t)3*HH;

    float* out = (float*)d_out;
    float* Z0 = out;                      float* Z1 = out + (size_t)4194304;
    float* Z2 = out + (size_t)8388608;    float* Z3 = out + (size_t)10485760;
    float* FD0 = out + (size_t)11534336;  float* FD1 = out + (size_t)12582912;
    float* FD2 = out + (size_t)14680064;  float* FD3 = out + (size_t)18874368;

    cudaFuncSetAttribute(attn_kernel, cudaFuncAttributeMaxDynamicSharedMemorySize, 131072);
    cudaFuncSetAttribute(gemm_fp16, cudaFuncAttributeMaxDynamicSharedMemorySize, GEMM_SM);

    dim3 b32(32, 8);
    transpose2d_kernel<<<dim3(32, 72, 4), b32>>>(xT, x, 2304, 1024);
    wsplit_kernel<<<dim3(32, 32, 16), b32>>>(W + oE,  W + WTOT + oE,  enc_qkvo, 1024, 1024);
    wsplit_kernel<<<dim3(32, 32, 4),  b32>>>(W + oD0, W + WTOT + oD0, dq0,      1024, 1024);
    wsplit_kernel<<<dim3(32, 32, 12), b32>>>(W + oD1, W + WTOT + oD1, da1,      1024, 1024);
    wsplit_kernel<<<dim3(32, 32, 12), b32>>>(W + oD2, W + WTOT + oD2, da2,      1024, 1024);
    wsplit_kernel<<<dim3(128, 32, 4), b32>>>(W + oF1e, W + WTOT + oF1e, ef1, 1024, 4096);
    wsplit_kernel<<<dim3(32, 128, 4), b32>>>(W + oF2e, W + WTOT + oF2e, ef2, 4096, 1024);
    wsplit_kernel<<<dim3(128, 32, 3), b32>>>(W + oF1d, W + WTOT + oF1d, df1, 1024, 4096);
    wsplit_kernel<<<dim3(32, 128, 3), b32>>>(W + oF2d, W + WTOT + oF2d, df2, 4096, 1024);
    convw_split_kernel<<<27648, 256>>>(W + oWe, W + WTOT + oWe, emb_w, 2304, 7077888);
    convw_split_kernel<<<12288, 256>>>(W + oWc, W + WTOT + oWc, conv0_w, 1024, 3*HH);
    deconvw_split_kernel<<<dim3(12288, 3), 256>>>(W + oWd, W + WTOT + oWd, ddw);

    auto G = [&](const __half* ah, const __half* al, size_t ow, float* C,
                 int M, int N, int K, const float* bias, int relu) {
        gemm_fp16<<<dim3(N/128, M/128), 256, GEMM_SM>>>(ah, al, W + ow, W + WTOT + ow,
                                                        C, M, N, K, bias, relu);
    };
    auto splitA = [&](const float* src, int n) {
        split_kernel<<<(n/4 + 255)/256, 256>>>(As, AsL, src, n/4);
    };

    im2col_split_kernel<<<(4096*6912/4 + 255)/256, 256>>>(im, imL, xT, 1024, 1024, 2304, 1, 0,
                                                          4096*6912/4);
    G(im, imL, oWe, bX, 4096, 1024, 6912, emb_b, 1);

    auto mha = [&](const float* xq, const float* xkv, size_t ow, int S, int wnd) {
        int rows = 4 * S;
        splitA(xq, rows * 1024);
        G(As, AsL, ow, bQ, rows, 1024, 1024, nullptr, 0);
        if (xkv != xq) splitA(xkv, rows * 1024);
        G(As, AsL, ow + (size_t)HH, bK, rows, 1024, 1024, nullptr, 0);
        G(As, AsL, ow + (size_t)2*HH, bV, rows, 1024, 1024, nullptr, 0);
        attn_kernel<<<dim3(S/128, NHnum, 4), 128, 131072>>>(bQ, bK, bV, bA, S, wnd);
        splitA(bA, rows * 1024);
        G(As, AsL, ow + (size_t)3*HH, bT, rows, 1024, 1024, nullptr, 0);
    };

    const int encS[4] = {1024, 1024, 512, 256};
    float* Zp[4] = {Z0, Z1, Z2, Z3};
    for (int i = 0; i < 4; i++) {
        int S = encS[i], rows = 4 * S;
        mha(bX, bX, oE + (size_t)i*4*HH, S, 1);
        const float* lnb = enc_ln + (size_t)i * 4096;
        ln_kernel<<<rows, 256>>>(bY, bX, bT, lnb, lnb + 1024);
        splitA(bY, rows * 1024);
        G(As, AsL, oF1e + (size_t)i*4*HH, bF, rows, 4096, 1024, eb1 + (size_t)i*4096, 1);
        splitA(bF, rows * 4096);
        G(As, AsL, oF2e + (size_t)i*4*HH, bT, rows, 1024, 4096, eb2 + (size_t)i*1024, 0);
        ln_kernel<<<rows, 256>>>(Zp[i], bY, bT, lnb + 2048, lnb + 3072);
        if (i == 0) {
            im2col_split_kernel<<<(rows*3072/4 + 255)/256, 256>>>(im, imL, Zp[i], S, S, 1024,
                                                                  1, 0, rows*3072/4);
            G(im, imL, oWc, bX, rows, 1024, 3072, conv0_b, 1);
        } else if (i < 3) {
            int S2 = S/2, n4 = 4*S2*256;
            poolrelu_kernel<<<(n4 + 255)/256, 256>>>(bX, Zp[i], S2, n4);
        }
    }

    mha(Z3, Z3, oD0, 256, 0);
    ln_kernel<<<1024, 256>>>(FD0, Z3, bT, dln0, dln0 + 1024);

    const float* fdPrev = FD0; int Sprev = 256;
    const float* feP[3] = {Z2, Z1, Z0};
    const int decS[3] = {512, 1024, 1024}, decSt[3] = {2, 2, 1};
    float* fdOut[3] = {FD1, FD2, FD3};
    for (int i = 0; i < 3; i++) {
        int S = decS[i], rows = 4 * S;
        im2col_split_kernel<<<(rows*3072/4 + 255)/256, 256>>>(im, imL, fdPrev, S, Sprev, 1024,
                                                              decSt[i], 1, rows*3072/4);
        G(im, imL, oWd + (size_t)i*3*HH, bD, rows, 1024, 3072, ddb + (size_t)i*1024, 1);
        const float* lnb = dln + (size_t)i * 6144;
        mha(feP[i], bD, oD1 + (size_t)i*4*HH, S, 0);
        ln_kernel<<<rows, 256>>>(bY, feP[i], bT, lnb, lnb + 1024);
        mha(bD, feP[i], oD2 + (size_t)i*4*HH, S, 0);
        ln_kernel<<<rows, 256>>>(bY2, bD, bT, lnb + 2048, lnb + 3072);
        int n4 = rows * 256;
        add_kernel<<<(n4 + 255)/256, 256>>>(bZ, bY, bY2, n4);
        splitA(bZ, rows * 1024);
        G(As, AsL, oF1d + (size_t)i*4*HH, bF, rows, 4096, 1024, db1 + (size_t)i*4096, 1);
        splitA(bF, rows * 4096);
        G(As, AsL, oF2d + (size_t)i*4*HH, bT, rows, 1024, 4096, db2 + (size_t)i*1024, 0);
        ln_kernel<<<rows, 256>>>(fdOut[i], bZ, bT, lnb + 4096, lnb + 5120);
        fdPrev = fdOut[i]; Sprev = S;
    }
}

// round 8
// speedup vs baseline: 2.4554x; 1.8078x over previous
#include <cuda_runtime.h>
#include <cuda_fp16.h>
#include <cstdint>
#include <cstddef>

#define HH (1024*1024)
#define NHnum 16
#define WTOT ((size_t)124518400)
#define IMLO ((size_t)28311552)
#define ASLO ((size_t)16777216)

__device__ __half g_W [(size_t)2*WTOT];
__device__ __half g_im[(size_t)2*28311552];
__device__ __half g_As[(size_t)2*16777216];
__device__ __half g_at[(size_t)8*4194304];
__device__ float  g_xT[(size_t)9437184];
__device__ float  g_buf[(size_t)56*HH];

__device__ __forceinline__ void sp2(float a, float b, __half2* hi, __half2* lo)
{
    __half2 h = __floats2half2_rn(a, b);
    float2 f = __half22float2(h);
    *hi = h;
    *lo = __floats2half2_rn(a - f.x, b - f.y);
}

// ---------------- prep kernels ----------------
__global__ void transpose2d_kernel(float* dst, const float* src, int R, int C)
{
    __shared__ float tile[32][33];
    int b = blockIdx.z;
    const float* s = src + (size_t)b * R * C;
    float* d = dst + (size_t)b * R * C;
    int c0 = blockIdx.x * 32, r0 = blockIdx.y * 32, tx = threadIdx.x, ty = threadIdx.y;
    for (int i = 0; i < 32; i += 8) tile[ty + i][tx] = s[(size_t)(r0 + ty + i) * C + c0 + tx];
    __syncthreads();
    for (int i = 0; i < 32; i += 8) d[(size_t)(c0 + ty + i) * R + r0 + tx] = tile[tx][ty + i];
}

__global__ void wsplit_kernel(__half* hi, __half* lo, const float* src, int K, int N)
{
    __shared__ float tile[32][33];
    size_t mo = (size_t)blockIdx.z * K * N;
    int n0 = blockIdx.x * 32, k0 = blockIdx.y * 32, tx = threadIdx.x, ty = threadIdx.y;
    for (int i = 0; i < 32; i += 8) tile[ty + i][tx] = src[mo + (size_t)(k0 + ty + i) * N + n0 + tx];
    __syncthreads();
    for (int i = 0; i < 32; i += 8) {
        float x = tile[tx][ty + i];
        __half h = __float2half_rn(x);
        size_t o = mo + (size_t)(n0 + ty + i) * K + k0 + tx;
        hi[o] = h; lo[o] = __float2half_rn(x - __half2float(h));
    }
}

__global__ void convw_split_kernel(__half* hi, __half* lo, const float* src, int Cin, int total)
{
    int idx = blockIdx.x * 256 + threadIdx.x;
    if (idx >= total) return;
    int K = 3 * Cin;
    int n = idx / K, r = idx - n * K;
    int ks = r / Cin, c = r - ks * Cin;
    float x = src[((size_t)n * Cin + c) * 3 + ks];
    __half h = __float2half_rn(x);
    hi[idx] = h; lo[idx] = __float2half_rn(x - __half2float(h));
}

__global__ void deconvw_split_kernel(__half* hi, __half* lo, const float* src)
{
    int idx = blockIdx.x * 256 + threadIdx.x;
    int i = blockIdx.y;
    int o = idx / 3072, r = idx - o * 3072;
    int ks = r >> 10, c = r & 1023;
    float x = src[(size_t)i * 3 * HH + ((size_t)c * 1024 + o) * 3 + ks];
    __half h = __float2half_rn(x);
    size_t d = (size_t)i * 3 * HH + idx;
    hi[d] = h; lo[d] = __float2half_rn(x - __half2float(h));
}

__global__ void split_kernel(__half* hi, __half* lo, const float* src, int n4)
{
    int i = blockIdx.x * 256 + threadIdx.x;
    if (i >= n4) return;
    float4 v = ((const float4*)src)[i];
    __half2 h01, l01, h23, l23;
    sp2(v.x, v.y, &h01, &l01);
    sp2(v.z, v.w, &h23, &l23);
    *(__half2*)(hi + 4*(size_t)i)     = h01;
    *(__half2*)(hi + 4*(size_t)i + 2) = h23;
    *(__half2*)(lo + 4*(size_t)i)     = l01;
    *(__half2*)(lo + 4*(size_t)i + 2) = l23;
}

__global__ void im2col_split_kernel(__half* hi, __half* lo, const float* In,
                                    int Tout, int Tin, int Cin, int stride, int mode, int total4)
{
    int idx = blockIdx.x * 256 + threadIdx.x;
    if (idx >= total4) return;
    int kw = 3 * Cin / 4, cq4 = Cin / 4;
    int kq = idx % kw, m = idx / kw;
    int ks = kq / cq4, c4 = kq - ks * cq4;
    int b = m / Tout, tt = m - b * Tout;
    float4 v = make_float4(0.f, 0.f, 0.f, 0.f);
    int tin = -1;
    if (mode == 0) { int ti = tt + ks - 1; if (ti >= 0 && ti < Tin) tin = ti; }
    else { int num = tt + 1 - ks;
           if (num >= 0 && num % stride == 0) { int ti = num / stride; if (ti < Tin) tin = ti; } }
    if (tin >= 0) v = *(const float4*)(In + ((size_t)(b * Tin + tin) * Cin + c4 * 4));
    __half2 h01, l01, h23, l23;
    sp2(v.x, v.y, &h01, &l01);
    sp2(v.z, v.w, &h23, &l23);
    *(__half2*)(hi + 4*(size_t)idx)     = h01;
    *(__half2*)(hi + 4*(size_t)idx + 2) = h23;
    *(__half2*)(lo + 4*(size_t)idx)     = l01;
    *(__half2*)(lo + 4*(size_t)idx + 2) = l23;
}

// ---------------- common MMA macros ----------------
#define GEMM_SM 81920
#define CP16(d, s) asm volatile("cp.async.ca.shared.global [%0], [%1], 16;" :: "r"(d), "l"(s))
#define LDSM4(r, a) asm volatile( \
    "ldmatrix.sync.aligned.m8n8.x4.shared.b16 {%0,%1,%2,%3}, [%4];" \
    : "=r"((r)[0]), "=r"((r)[1]), "=r"((r)[2]), "=r"((r)[3]) : "r"(a))
#define LDSM4T(r, a) asm volatile( \
    "ldmatrix.sync.aligned.m8n8.x4.trans.shared.b16 {%0,%1,%2,%3}, [%4];" \
    : "=r"((r)[0]), "=r"((r)[1]), "=r"((r)[2]), "=r"((r)[3]) : "r"(a))
#define MMA16(d, A_, B_) asm volatile( \
    "mma.sync.aligned.m16n8k16.row.col.f32.f16.f16.f32 " \
    "{%0,%1,%2,%3},{%4,%5,%6,%7},{%8,%9},{%0,%1,%2,%3};" \
    : "+f"((d)[0]), "+f"((d)[1]), "+f"((d)[2]), "+f"((d)[3]) \
    : "r"((A_)[0]), "r"((A_)[1]), "r"((A_)[2]), "r"((A_)[3]), "r"((B_)[0]), "r"((B_)[1]))

// ---------------- fp16x2-split tensor GEMM ----------------
__global__ __launch_bounds__(256) void gemm_fp16(
    const __half* Ah, const __half* Al, const __half* Bh, const __half* Bl,
    float* C, __half* Ch, __half* Cl,
    int M, int N, int K, const float* bias, int relu)
{
    extern __shared__ char smc[];
    const uint32_t smb = (uint32_t)__cvta_generic_to_shared(smc);
    const int t = threadIdx.x, lane = t & 31, wid = t >> 5;
    const int wm = wid & 1, wn = wid >> 1;
    const int bx = blockIdx.x, by = blockIdx.y;

    float acc[4][4][4];
    #pragma unroll
    for (int a = 0; a < 4; a++)
        #pragma unroll
        for (int b = 0; b < 4; b++)
            #pragma unroll
            for (int c = 0; c < 4; c++) acc[a][b][c] = 0.f;

    const __half* P[4] = {Ah, Al, Bh, Bl};
    const int KT = K >> 5;

    auto LD = [&](int s, int k0) {
        uint32_t sb = smb + (uint32_t)s * 40960u;
        #pragma unroll
        for (int p = 0; p < 4; p++) {
            const __half* src = P[p] + (size_t)((p < 2 ? by : bx) * 128) * K + k0;
            #pragma unroll
            for (int i = 0; i < 2; i++) {
                int idx = i * 256 + t, r = idx >> 2, c = idx & 3;
                CP16(sb + (uint32_t)p * 10240u + (uint32_t)(r * 80 + c * 16),
                     src + (size_t)r * K + c * 8);
            }
        }
    };

    auto COMP = [&](int s) {
        uint32_t sb = smb + (uint32_t)s * 40960u;
        const int arow = wm * 64 + (lane & 7) + ((lane >> 3) & 1) * 8;
        const int brow = wn * 32 + (lane & 7) + ((lane >> 4) & 1) * 8;
        #pragma unroll
        for (int kk = 0; kk < 2; kk++) {
            uint32_t ah[4][4], al[4][4], bh[4][2], bl[4][2];
            const int achk = kk * 2 + (lane >> 4);
            const int bchk = kk * 2 + ((lane >> 3) & 1);
            #pragma unroll
            for (int mt = 0; mt < 4; mt++) {
                uint32_t ad = sb + (uint32_t)((arow + mt * 16) * 80 + achk * 16);
                LDSM4(ah[mt], ad);
                LDSM4(al[mt], ad + 10240u);
            }
            #pragma unroll
            for (int np = 0; np < 2; np++) {
                uint32_t bd = sb + 20480u + (uint32_t)((brow + np * 16) * 80 + bchk * 16);
                uint32_t r4[4];
                LDSM4(r4, bd);
                bh[np*2][0] = r4[0]; bh[np*2][1] = r4[1];
                bh[np*2+1][0] = r4[2]; bh[np*2+1][1] = r4[3];
                LDSM4(r4, bd + 10240u);
                bl[np*2][0] = r4[0]; bl[np*2][1] = r4[1];
                bl[np*2+1][0] = r4[2]; bl[np*2+1][1] = r4[3];
            }
            #pragma unroll
            for (int mt = 0; mt < 4; mt++)
                #pragma unroll
                for (int nt = 0; nt < 4; nt++) {
                    MMA16(acc[mt][nt], ah[mt], bh[nt]);
                    MMA16(acc[mt][nt], al[mt], bh[nt]);
                    MMA16(acc[mt][nt], ah[mt], bl[nt]);
                }
        }
    };

    LD(0, 0);
    asm volatile("cp.async.commit_group;");
    for (int kt = 0; kt < KT; kt++) {
        if (kt + 1 < KT) {
            LD((kt + 1) & 1, (kt + 1) << 5);
            asm volatile("cp.async.commit_group;");
            asm volatile("cp.async.wait_group 1;");
        } else {
            asm volatile("cp.async.wait_group 0;");
        }
        __syncthreads();
        COMP(kt & 1);
        __syncthreads();
    }

    const int lr = lane >> 2, lc = (lane & 3) * 2;
    #pragma unroll
    for (int mt = 0; mt < 4; mt++) {
        int r0 = by * 128 + wm * 64 + mt * 16 + lr;
        #pragma unroll
        for (int nt = 0; nt < 4; nt++) {
            int c0 = bx * 128 + wn * 32 + nt * 8 + lc;
            if (Ch) {
                __half2 hh, ll;
                sp2(acc[mt][nt][0], acc[mt][nt][1], &hh, &ll);
                *(__half2*)(Ch + (size_t)r0 * N + c0) = hh;
                *(__half2*)(Cl + (size_t)r0 * N + c0) = ll;
                sp2(acc[mt][nt][2], acc[mt][nt][3], &hh, &ll);
                *(__half2*)(Ch + (size_t)(r0 + 8) * N + c0) = hh;
                *(__half2*)(Cl + (size_t)(r0 + 8) * N + c0) = ll;
            } else {
                float b0 = 0.f, b1 = 0.f;
                if (bias) { float2 bv = *(const float2*)(bias + c0); b0 = bv.x; b1 = bv.y; }
                float v0 = acc[mt][nt][0] + b0, v1 = acc[mt][nt][1] + b1;
                float v2 = acc[mt][nt][2] + b0, v3 = acc[mt][nt][3] + b1;
                if (relu) { v0 = fmaxf(v0,0.f); v1 = fmaxf(v1,0.f);
                            v2 = fmaxf(v2,0.f); v3 = fmaxf(v3,0.f); }
                *(float2*)(C + (size_t)r0 * N + c0)       = make_float2(v0, v1);
                *(float2*)(C + (size_t)(r0 + 8) * N + c0) = make_float2(v2, v3);
            }
        }
    }
}

// ---------------- tensor-core flash attention (fp16 split) ----------------
// CTA: 128 queries x 1 head x 1 batch.  8 warps x 16 rows.  D=64.
// smem: Q planes (2x18432) | KV stages (2x): Kh|Kl|Vh|Vl (4x18432). pitch 144B.
#define AT_SM 184320
__global__ __launch_bounds__(256) void attn_tc(
    const __half* Qh, const __half* Ql, const __half* Kh, const __half* Kl,
    const __half* Vh, const __half* Vl, __half* Oh, __half* Ol,
    int S, int windowed)
{
    extern __shared__ char smc[];
    const uint32_t sb = (uint32_t)__cvta_generic_to_shared(smc);
    const int t = threadIdx.x, lane = t & 31, w = t >> 5;
    const int lr = lane >> 2, lc = lane & 3;
    const int qb = blockIdx.x, h = blockIdx.y, b = blockIdx.z;
    const size_t qbase = ((size_t)b * S + qb * 128) * 1024 + h * 64;

    for (int i = t; i < 1024; i += 256) {
        int r = i >> 3, c = i & 7;
        size_t go = qbase + (size_t)r * 1024 + c * 8;
        uint32_t so = (uint32_t)(r * 144 + c * 16);
        CP16(sb + so,          Qh + go);
        CP16(sb + 18432u + so, Ql + go);
    }
    asm volatile("cp.async.commit_group;");

    const int nb = windowed ? 1 : (S >> 7);
    const int jb0 = windowed ? qb : 0;

    auto ldkv = [&](int jb, int st) {
        uint32_t kb = sb + 36864u + (uint32_t)st * 73728u;
        size_t gb = ((size_t)b * S + jb * 128) * 1024 + h * 64;
        for (int i = t; i < 1024; i += 256) {
            int r = i >> 3, c = i & 7;
            size_t go = gb + (size_t)r * 1024 + c * 8;
            uint32_t so = (uint32_t)(r * 144 + c * 16);
            CP16(kb + so,           Kh + go);
            CP16(kb + 18432u + so,  Kl + go);
            CP16(kb + 36864u + so,  Vh + go);
            CP16(kb + 55296u + so,  Vl + go);
        }
    };

    ldkv(jb0, 0);
    asm volatile("cp.async.commit_group;");
    asm volatile("cp.async.wait_group 1;");
    __syncthreads();

    uint32_t qfh[4][4], qfl[4][4];
    {
        uint32_t qrow = (uint32_t)(w * 16 + (lane & 7) + ((lane >> 3) & 1) * 8);
        #pragma unroll
        for (int kc = 0; kc < 4; kc++) {
            uint32_t qa = sb + qrow * 144u + (uint32_t)((kc * 2 + (lane >> 4)) * 16);
            LDSM4(qfh[kc], qa);
            LDSM4(qfl[kc], qa + 18432u);
        }
    }

    float oacc[8][4];
    #pragma unroll
    for (int j = 0; j < 8; j++)
        #pragma unroll
        for (int c = 0; c < 4; c++) oacc[j][c] = 0.f;
    float m0 = -1e30f, m1 = -1e30f, l0 = 0.f, l1 = 0.f;

    for (int i = 0; i < nb; i++) {
        if (i + 1 < nb) {
            ldkv(jb0 + i + 1, (i + 1) & 1);
            asm volatile("cp.async.commit_group;");
            asm volatile("cp.async.wait_group 1;");
        } else {
            asm volatile("cp.async.wait_group 0;");
        }
        __syncthreads();
        uint32_t kb = sb + 36864u + (uint32_t)(i & 1) * 73728u;

        float sacc[16][4];
        #pragma unroll
        for (int nt = 0; nt < 16; nt++)
            #pragma unroll
            for (int c = 0; c < 4; c++) sacc[nt][c] = 0.f;

        const uint32_t krow = (uint32_t)((lane & 7) + ((lane >> 4) & 1) * 8);
        const uint32_t kchk = (uint32_t)((lane >> 3) & 1);
        #pragma unroll
        for (int np = 0; np < 8; np++) {
            #pragma unroll
            for (int kc = 0; kc < 4; kc++) {
                uint32_t ka = kb + (np * 16 + krow) * 144u + (kc * 2 + kchk) * 16u;
                uint32_t bh4[4], bl4[4];
                LDSM4(bh4, ka);
                LDSM4(bl4, ka + 18432u);
                MMA16(sacc[2*np],   qfh[kc], &bh4[0]);
                MMA16(sacc[2*np],   qfl[kc], &bh4[0]);
                MMA16(sacc[2*np],   qfh[kc], &bl4[0]);
                MMA16(sacc[2*np+1], qfh[kc], &bh4[2]);
                MMA16(sacc[2*np+1], qfl[kc], &bh4[2]);
                MMA16(sacc[2*np+1], qfh[kc], &bl4[2]);
            }
        }

        // softmax (online, register fragments)
        float mx0 = -1e30f, mx1 = -1e30f;
        #pragma unroll
        for (int nt = 0; nt < 16; nt++) {
            sacc[nt][0] *= 0.125f; sacc[nt][1] *= 0.125f;
            sacc[nt][2] *= 0.125f; sacc[nt][3] *= 0.125f;
            mx0 = fmaxf(mx0, fmaxf(sacc[nt][0], sacc[nt][1]));
            mx1 = fmaxf(mx1, fmaxf(sacc[nt][2], sacc[nt][3]));
        }
        mx0 = fmaxf(mx0, __shfl_xor_sync(0xffffffffu, mx0, 1));
        mx0 = fmaxf(mx0, __shfl_xor_sync(0xffffffffu, mx0, 2));
        mx1 = fmaxf(mx1, __shfl_xor_sync(0xffffffffu, mx1, 1));
        mx1 = fmaxf(mx1, __shfl_xor_sync(0xffffffffu, mx1, 2));
        float nm0 = fmaxf(m0, mx0), nm1 = fmaxf(m1, mx1);
        float cr0 = __expf(m0 - nm0), cr1 = __expf(m1 - nm1);
        l0 *= cr0; l1 *= cr1;
        #pragma unroll
        for (int j = 0; j < 8; j++) {
            oacc[j][0] *= cr0; oacc[j][1] *= cr0;
            oacc[j][2] *= cr1; oacc[j][3] *= cr1;
        }
        float rs0 = 0.f, rs1 = 0.f;
        #pragma unroll
        for (int nt = 0; nt < 16; nt++) {
            float p0 = __expf(sacc[nt][0] - nm0), p1 = __expf(sacc[nt][1] - nm0);
            float p2 = __expf(sacc[nt][2] - nm1), p3 = __expf(sacc[nt][3] - nm1);
            sacc[nt][0] = p0; sacc[nt][1] = p1; sacc[nt][2] = p2; sacc[nt][3] = p3;
            rs0 += p0 + p1; rs1 += p2 + p3;
        }
        rs0 += __shfl_xor_sync(0xffffffffu, rs0, 1);
        rs0 += __shfl_xor_sync(0xffffffffu, rs0, 2);
        rs1 += __shfl_xor_sync(0xffffffffu, rs1, 1);
        rs1 += __shfl_xor_sync(0xffffffffu, rs1, 2);
        l0 += rs0; l1 += rs1; m0 = nm0; m1 = nm1;

        // P @ V
        const uint32_t vrow = (uint32_t)((lane & 7) + ((lane >> 3) & 1) * 8);
        const uint32_t vchk = (uint32_t)((lane >> 4) & 1);
        #pragma unroll
        for (int kc = 0; kc < 8; kc++) {
            uint32_t ph[4], pl[4];
            #pragma unroll
            for (int q = 0; q < 2; q++) {
                __half2 hh, ll;
                sp2(sacc[2*kc+q][0], sacc[2*kc+q][1], &hh, &ll);
                ph[q*2]   = *(uint32_t*)&hh; pl[q*2]   = *(uint32_t*)&ll;
                sp2(sacc[2*kc+q][2], sacc[2*kc+q][3], &hh, &ll);
                ph[q*2+1] = *(uint32_t*)&hh; pl[q*2+1] = *(uint32_t*)&ll;
            }
            #pragma unroll
            for (int p4 = 0; p4 < 4; p4++) {
                uint32_t va = kb + 36864u + (kc * 16 + vrow) * 144u + p4 * 32u + vchk * 16u;
                uint32_t vh4[4], vl4[4];
                LDSM4T(vh4, va);
                LDSM4T(vl4, va + 18432u);
                MMA16(oacc[2*p4],   ph, &vh4[0]);
                MMA16(oacc[2*p4],   pl, &vh4[0]);
                MMA16(oacc[2*p4],   ph, &vl4[0]);
                MMA16(oacc[2*p4+1], ph, &vh4[2]);
                MMA16(oacc[2*p4+1], pl, &vh4[2]);
                MMA16(oacc[2*p4+1], ph, &vl4[2]);
            }
        }
        __syncthreads();
    }

    const float i0 = 1.f / l0, i1 = 1.f / l1;
    #pragma unroll
    for (int j = 0; j < 8; j++) {
        size_t o0 = qbase + (size_t)(w * 16 + lr) * 1024 + j * 8 + lc * 2;
        __half2 hh, ll;
        sp2(oacc[j][0] * i0, oacc[j][1] * i0, &hh, &ll);
        *(__half2*)(Oh + o0) = hh; *(__half2*)(Ol + o0) = ll;
        sp2(oacc[j][2] * i1, oacc[j][3] * i1, &hh, &ll);
        *(__half2*)(Oh + o0 + 8192) = hh; *(__half2*)(Ol + o0 + 8192) = ll;
    }
}

// ---------------- ln / pool / add ----------------
__global__ __launch_bounds__(256) void ln_kernel(
    float* out, const float* in1, const float* in2, const float* g, const float* be)
{
    __shared__ float rs[8], rss[8];
    const int row = blockIdx.x, tid = threadIdx.x;
    const size_t base = (size_t)row * 1024 + tid * 4;
    float4 a = *(const float4*)(in1 + base), b2 = *(const float4*)(in2 + base);
    a.x += b2.x; a.y += b2.y; a.z += b2.z; a.w += b2.w;
    float s = a.x + a.y + a.z + a.w;
    float ss = a.x*a.x + a.y*a.y + a.z*a.z + a.w*a.w;
    for (int o = 16; o > 0; o >>= 1) {
        s += __shfl_xor_sync(0xffffffffu, s, o);
        ss += __shfl_xor_sync(0xffffffffu, ss, o);
    }
    if ((tid & 31) == 0) { rs[tid >> 5] = s; rss[tid >> 5] = ss; }
    __syncthreads();
    float st = 0.f, sst = 0.f;
    for (int i = 0; i < 8; i++) { st += rs[i]; sst += rss[i]; }
    const float mean = st * (1.f/1024.f), var = sst * (1.f/1024.f) - mean*mean;
    const float inv = rsqrtf(var + 1e-5f);
    float4 gg = *(const float4*)(g + tid*4), bb = *(const float4*)(be + tid*4), o4;
    o4.x = (a.x-mean)*inv*gg.x + bb.x; o4.y = (a.y-mean)*inv*gg.y + bb.y;
    o4.z = (a.z-mean)*inv*gg.z + bb.z; o4.w = (a.w-mean)*inv*gg.w + bb.w;
    *(float4*)(out + base) = o4;
}

__global__ void poolrelu_kernel(float* out, const float* in, int S2, int n4)
{
    int idx = blockIdx.x * blockDim.x + threadIdx.x;
    if (idx >= n4) return;
    int h4 = idx & 255, bt = idx >> 8, b = bt / S2, t2 = bt - b * S2;
    const float4* i0 = (const float4*)in + ((size_t)(b*S2*2 + t2*2) * 256 + h4);
    float4 a = i0[0], c = i0[256], o;
    o.x = fmaxf(fmaxf(a.x,c.x),0.f); o.y = fmaxf(fmaxf(a.y,c.y),0.f);
    o.z = fmaxf(fmaxf(a.z,c.z),0.f); o.w = fmaxf(fmaxf(a.w,c.w),0.f);
    ((float4*)out)[idx] = o;
}

__global__ void add_kernel(float* out, const float* a, const float* b, int n4)
{
    int i = blockIdx.x * blockDim.x + threadIdx.x;
    if (i >= n4) return;
    float4 x = ((const float4*)a)[i], y = ((const float4*)b)[i];
    ((float4*)out)[i] = make_float4(x.x+y.x, x.y+y.y, x.z+y.z, x.w+y.w);
}

// ---------------- host ----------------
extern "C" void kernel_launch(void* const* d_in, const int* in_sizes, int n_in,
                              void* d_out, int out_size)
{
    (void)in_sizes; (void)n_in; (void)out_size;
    const float* x        = (const float*)d_in[0];
    const float* emb_w    = (const float*)d_in[1];
    const float* emb_b    = (const float*)d_in[2];
    const float* enc_qkvo = (const float*)d_in[3];
    const float* enc_ln   = (const float*)d_in[4];
    const float* ef1      = (const float*)d_in[5];
    const float* eb1      = (const float*)d_in[6];
    const float* ef2      = (const float*)d_in[7];
    const float* eb2      = (const float*)d_in[8];
    const float* conv0_w  = (const float*)d_in[9];
    const float* conv0_b  = (const float*)d_in[10];
    const float* dq0      = (const float*)d_in[11];
    const float* dln0     = (const float*)d_in[12];
    const float* da1      = (const float*)d_in[13];
    const float* da2      = (const float*)d_in[14];
    const float* dln      = (const float*)d_in[15];
    const float* df1      = (const float*)d_in[16];
    const float* db1      = (const float*)d_in[17];
    const float* df2      = (const float*)d_in[18];
    const float* db2      = (const float*)d_in[19];
    const float* ddw      = (const float*)d_in[20];
    const float* ddb      = (const float*)d_in[21];

    __half *W, *im, *As, *at;
    float *xT, *buf;
    cudaGetSymbolAddress((void**)&W,  g_W);
    cudaGetSymbolAddress((void**)&im, g_im);
    cudaGetSymbolAddress((void**)&As, g_As);
    cudaGetSymbolAddress((void**)&at, g_at);
    cudaGetSymbolAddress((void**)&xT, g_xT);
    cudaGetSymbolAddress((void**)&buf, g_buf);

    float *bX = buf, *bT = buf+(size_t)20*HH, *bY = buf+(size_t)24*HH,
          *bD = buf+(size_t)28*HH, *bY2 = buf+(size_t)32*HH, *bZ = buf+(size_t)36*HH,
          *bF = buf+(size_t)40*HH;
    __half *AsL = As + ASLO, *imL = im + IMLO;
    __half *Qh_ = at,              *Ql_ = at + (size_t)4*HH,
           *Kh_ = at + (size_t)8*HH,  *Kl_ = at + (size_t)12*HH,
           *Vh_ = at + (size_t)16*HH, *Vl_ = at + (size_t)20*HH,
           *Ah_ = at + (size_t)24*HH, *Al_ = at + (size_t)28*HH;

    const size_t oE = 0, oD0 = (size_t)16*HH, oD1 = (size_t)20*HH, oD2 = (size_t)32*HH,
                 oF1e = (size_t)44*HH, oF2e = (size_t)60*HH, oF1d = (size_t)76*HH,
                 oF2d = (size_t)88*HH, oWe = (size_t)100*HH,
                 oWc = oWe + 7077888, oWd = oWc + (size_t)3*HH;

    float* out = (float*)d_out;
    float* Z0 = out;                      float* Z1 = out + (size_t)4194304;
    float* Z2 = out + (size_t)8388608;    float* Z3 = out + (size_t)10485760;
    float* FD0 = out + (size_t)11534336;  float* FD1 = out + (size_t)12582912;
    float* FD2 = out + (size_t)14680064;  float* FD3 = out + (size_t)18874368;

    cudaFuncSetAttribute(attn_tc, cudaFuncAttributeMaxDynamicSharedMemorySize, AT_SM);
    cudaFuncSetAttribute(gemm_fp16, cudaFuncAttributeMaxDynamicSharedMemorySize, GEMM_SM);

    dim3 b32(32, 8);
    transpose2d_kernel<<<dim3(32, 72, 4), b32>>>(xT, x, 2304, 1024);
    wsplit_kernel<<<dim3(32, 32, 16), b32>>>(W + oE,  W + WTOT + oE,  enc_qkvo, 1024, 1024);
    wsplit_kernel<<<dim3(32, 32, 4),  b32>>>(W + oD0, W + WTOT + oD0, dq0,      1024, 1024);
    wsplit_kernel<<<dim3(32, 32, 12), b32>>>(W + oD1, W + WTOT + oD1, da1,      1024, 1024);
    wsplit_kernel<<<dim3(32, 32, 12), b32>>>(W + oD2, W + WTOT + oD2, da2,      1024, 1024);
    wsplit_kernel<<<dim3(128, 32, 4), b32>>>(W + oF1e, W + WTOT + oF1e, ef1, 1024, 4096);
    wsplit_kernel<<<dim3(32, 128, 4), b32>>>(W + oF2e, W + WTOT + oF2e, ef2, 4096, 1024);
    wsplit_kernel<<<dim3(128, 32, 3), b32>>>(W + oF1d, W + WTOT + oF1d, df1, 1024, 4096);
    wsplit_kernel<<<dim3(32, 128, 3), b32>>>(W + oF2d, W + WTOT + oF2d, df2, 4096, 1024);
    convw_split_kernel<<<27648, 256>>>(W + oWe, W + WTOT + oWe, emb_w, 2304, 7077888);
    convw_split_kernel<<<12288, 256>>>(W + oWc, W + WTOT + oWc, conv0_w, 1024, 3*HH);
    deconvw_split_kernel<<<dim3(12288, 3), 256>>>(W + oWd, W + WTOT + oWd, ddw);

    auto G = [&](const __half* ah, const __half* al, size_t ow, float* C,
                 int M, int N, int K, const float* bias, int relu) {
        gemm_fp16<<<dim3(N/128, M/128), 256, GEMM_SM>>>(ah, al, W + ow, W + WTOT + ow,
                                                        C, nullptr, nullptr, M, N, K, bias, relu);
    };
    auto Gp = [&](const __half* ah, const __half* al, size_t ow, __half* Ch, __half* Cl,
                  int M, int N, int K) {
        gemm_fp16<<<dim3(N/128, M/128), 256, GEMM_SM>>>(ah, al, W + ow, W + WTOT + ow,
                                                        nullptr, Ch, Cl, M, N, K, nullptr, 0);
    };
    auto splitA = [&](const float* src, int n) {
        split_kernel<<<(n/4 + 255)/256, 256>>>(As, AsL, src, n/4);
    };

    im2col_split_kernel<<<(4096*6912/4 + 255)/256, 256>>>(im, imL, xT, 1024, 1024, 2304, 1, 0,
                                                          4096*6912/4);
    G(im, imL, oWe, bX, 4096, 1024, 6912, emb_b, 1);

    auto mha = [&](const float* xq, const float* xkv, size_t ow, int S, int wnd) {
        int rows = 4 * S;
        splitA(xq, rows * 1024);
        Gp(As, AsL, ow, Qh_, Ql_, rows, 1024, 1024);
        if (xkv != xq) splitA(xkv, rows * 1024);
        Gp(As, AsL, ow + (size_t)HH,   Kh_, Kl_, rows, 1024, 1024);
        Gp(As, AsL, ow + (size_t)2*HH, Vh_, Vl_, rows, 1024, 1024);
        attn_tc<<<dim3(S/128, NHnum, 4), 256, AT_SM>>>(Qh_, Ql_, Kh_, Kl_, Vh_, Vl_,
                                                       Ah_, Al_, S, wnd);
        G(Ah_, Al_, ow + (size_t)3*HH, bT, rows, 1024, 1024, nullptr, 0);
    };

    const int encS[4] = {1024, 1024, 512, 256};
    float* Zp[4] = {Z0, Z1, Z2, Z3};
    for (int i = 0; i < 4; i++) {
        int S = encS[i], rows = 4 * S;
        mha(bX, bX, oE + (size_t)i*4*HH, S, 1);
        const float* lnb = enc_ln + (size_t)i * 4096;
        ln_kernel<<<rows, 256>>>(bY, bX, bT, lnb, lnb + 1024);
        splitA(bY, rows * 1024);
        G(As, AsL, oF1e + (size_t)i*4*HH, bF, rows, 4096, 1024, eb1 + (size_t)i*4096, 1);
        splitA(bF, rows * 4096);
        G(As, AsL, oF2e + (size_t)i*4*HH, bT, rows, 1024, 4096, eb2 + (size_t)i*1024, 0);
        ln_kernel<<<rows, 256>>>(Zp[i], bY, bT, lnb + 2048, lnb + 3072);
        if (i == 0) {
            im2col_split_kernel<<<(rows*3072/4 + 255)/256, 256>>>(im, imL, Zp[i], S, S, 1024,
                                                                  1, 0, rows*3072/4);
            G(im, imL, oWc, bX, rows, 1024, 3072, conv0_b, 1);
        } else if (i < 3) {
            int S2 = S/2, n4 = 4*S2*256;
            poolrelu_kernel<<<(n4 + 255)/256, 256>>>(bX, Zp[i], S2, n4);
        }
    }

    mha(Z3, Z3, oD0, 256, 0);
    ln_kernel<<<1024, 256>>>(FD0, Z3, bT, dln0, dln0 + 1024);

    const float* fdPrev = FD0; int Sprev = 256;
    const float* feP[3] = {Z2, Z1, Z0};
    const int decS[3] = {512, 1024, 1024}, decSt[3] = {2, 2, 1};
    float* fdOut[3] = {FD1, FD2, FD3};
    for (int i = 0; i < 3; i++) {
        int S = decS[i], rows = 4 * S;
        im2col_split_kernel<<<(rows*3072/4 + 255)/256, 256>>>(im, imL, fdPrev, S, Sprev, 1024,
                                                              decSt[i], 1, rows*3072/4);
        G(im, imL, oWd + (size_t)i*3*HH, bD, rows, 1024, 3072, ddb + (size_t)i*1024, 1);
        const float* lnb = dln + (size_t)i * 6144;
        mha(feP[i], bD, oD1 + (size_t)i*4*HH, S, 0);
        ln_kernel<<<rows, 256>>>(bY, feP[i], bT, lnb, lnb + 1024);
        mha(bD, feP[i], oD2 + (size_t)i*4*HH, S, 0);
        ln_kernel<<<rows, 256>>>(bY2, bD, bT, lnb + 2048, lnb + 3072);
        int n4 = rows * 256;
        add_kernel<<<(n4 + 255)/256, 256>>>(bZ, bY, bY2, n4);
        splitA(bZ, rows * 1024);
        G(As, AsL, oF1d + (size_t)i*4*HH, bF, rows, 4096, 1024, db1 + (size_t)i*4096, 1);
        splitA(bF, rows * 4096);
        G(As, AsL, oF2d + (size_t)i*4*HH, bT, rows, 1024, 4096, db2 + (size_t)i*1024, 0);
        ln_kernel<<<rows, 256>>>(fdOut[i], bZ, bT, lnb + 4096, lnb + 5120);
        fdPrev = fdOut[i]; Sprev = S;
    }
}

// round 9
// speedup vs baseline: 2.5112x; 1.0227x over previous
#include <cuda_runtime.h>
#include <cuda_fp16.h>
#include <cstdint>
#include <cstddef>

#define HH (1024*1024)
#define WTOT ((size_t)124518400)
#define IMLO ((size_t)28311552)
#define ASLO ((size_t)16777216)
#define ZSLO ((size_t)11534336)

__device__ __half g_W [(size_t)2*WTOT];
__device__ __half g_im[(size_t)2*28311552];
__device__ __half g_As[(size_t)2*16777216];
__device__ __half g_Zs[(size_t)2*11534336];
__device__ __half g_at[(size_t)33554432];
__device__ float  g_xT[(size_t)9437184];
__device__ float  g_buf[(size_t)56*HH];

__device__ __forceinline__ void sp2(float a, float b, __half2* hi, __half2* lo)
{
    __half2 h = __floats2half2_rn(a, b);
    float2 f = __half22float2(h);
    *hi = h;
    *lo = __floats2half2_rn(a - f.x, b - f.y);
}

// ---------------- prep kernels ----------------
__global__ void transpose2d_kernel(float* dst, const float* src, int R, int C)
{
    __shared__ float tile[32][33];
    int b = blockIdx.z;
    const float* s = src + (size_t)b * R * C;
    float* d = dst + (size_t)b * R * C;
    int c0 = blockIdx.x * 32, r0 = blockIdx.y * 32, tx = threadIdx.x, ty = threadIdx.y;
    for (int i = 0; i < 32; i += 8) tile[ty + i][tx] = s[(size_t)(r0 + ty + i) * C + c0 + tx];
    __syncthreads();
    for (int i = 0; i < 32; i += 8) d[(size_t)(c0 + ty + i) * R + r0 + tx] = tile[tx][ty + i];
}

__global__ void wsplit_kernel(__half* hi, __half* lo, const float* src, int K, int N)
{
    __shared__ float tile[32][33];
    size_t mo = (size_t)blockIdx.z * K * N;
    int n0 = blockIdx.x * 32, k0 = blockIdx.y * 32, tx = threadIdx.x, ty = threadIdx.y;
    for (int i = 0; i < 32; i += 8) tile[ty + i][tx] = src[mo + (size_t)(k0 + ty + i) * N + n0 + tx];
    __syncthreads();
    for (int i = 0; i < 32; i += 8) {
        float x = tile[tx][ty + i];
        __half h = __float2half_rn(x);
        size_t o = mo + (size_t)(n0 + ty + i) * K + k0 + tx;
        hi[o] = h; lo[o] = __float2half_rn(x - __half2float(h));
    }
}

__global__ void convw_split_kernel(__half* hi, __half* lo, const float* src, int Cin, int total)
{
    int idx = blockIdx.x * 256 + threadIdx.x;
    if (idx >= total) return;
    int K = 3 * Cin;
    int n = idx / K, r = idx - n * K;
    int ks = r / Cin, c = r - ks * Cin;
    float x = src[((size_t)n * Cin + c) * 3 + ks];
    __half h = __float2half_rn(x);
    hi[idx] = h; lo[idx] = __float2half_rn(x - __half2float(h));
}

__global__ void deconvw_split_kernel(__half* hi, __half* lo, const float* src)
{
    int idx = blockIdx.x * 256 + threadIdx.x;
    int i = blockIdx.y;
    int o = idx / 3072, r = idx - o * 3072;
    int ks = r >> 10, c = r & 1023;
    float x = src[(size_t)i * 3 * HH + ((size_t)c * 1024 + o) * 3 + ks];
    __half h = __float2half_rn(x);
    size_t d = (size_t)i * 3 * HH + idx;
    hi[d] = h; lo[d] = __float2half_rn(x - __half2float(h));
}

__global__ void im2col_split_kernel(__half* hi, __half* lo, const float* In,
                                    int Tout, int Tin, int Cin, int stride, int mode, int total4)
{
    int idx = blockIdx.x * 256 + threadIdx.x;
    if (idx >= total4) return;
    int kw = 3 * Cin / 4, cq4 = Cin / 4;
    int kq = idx % kw, m = idx / kw;
    int ks = kq / cq4, c4 = kq - ks * cq4;
    int b = m / Tout, tt = m - b * Tout;
    float4 v = make_float4(0.f, 0.f, 0.f, 0.f);
    int tin = -1;
    if (mode == 0) { int ti = tt + ks - 1; if (ti >= 0 && ti < Tin) tin = ti; }
    else { int num = tt + 1 - ks;
           if (num >= 0 && num % stride == 0) { int ti = num / stride; if (ti < Tin) tin = ti; } }
    if (tin >= 0) v = *(const float4*)(In + ((size_t)(b * Tin + tin) * Cin + c4 * 4));
    __half2 h01, l01, h23, l23;
    sp2(v.x, v.y, &h01, &l01);
    sp2(v.z, v.w, &h23, &l23);
    *(__half2*)(hi + 4*(size_t)idx)     = h01;
    *(__half2*)(hi + 4*(size_t)idx + 2) = h23;
    *(__half2*)(lo + 4*(size_t)idx)     = l01;
    *(__half2*)(lo + 4*(size_t)idx + 2) = l23;
}

// ---------------- MMA macros ----------------
#define GEMM_SM 81920
#define CP16(d, s) asm volatile("cp.async.ca.shared.global [%0], [%1], 16;" :: "r"(d), "l"(s))
#define LDSM4(r, a) asm volatile( \
    "ldmatrix.sync.aligned.m8n8.x4.shared.b16 {%0,%1,%2,%3}, [%4];" \
    : "=r"((r)[0]), "=r"((r)[1]), "=r"((r)[2]), "=r"((r)[3]) : "r"(a))
#define LDSM4T(r, a) asm volatile( \
    "ldmatrix.sync.aligned.m8n8.x4.trans.shared.b16 {%0,%1,%2,%3}, [%4];" \
    : "=r"((r)[0]), "=r"((r)[1]), "=r"((r)[2]), "=r"((r)[3]) : "r"(a))
#define MMA16(d, A_, B_) asm volatile( \
    "mma.sync.aligned.m16n8k16.row.col.f32.f16.f16.f32 " \
    "{%0,%1,%2,%3},{%4,%5,%6,%7},{%8,%9},{%0,%1,%2,%3};" \
    : "+f"((d)[0]), "+f"((d)[1]), "+f"((d)[2]), "+f"((d)[3]) \
    : "r"((A_)[0]), "r"((A_)[1]), "r"((A_)[2]), "r"((A_)[3]), "r"((B_)[0]), "r"((B_)[1]))

// ---------------- fp16x2-split tensor GEMM ----------------
__global__ __launch_bounds__(256) void gemm_fp16(
    const __half* Ah, const __half* Al, const __half* Bh, const __half* Bl,
    float* Cf, __half* Ch, __half* Cl,
    int M, int N, int K, const float* bias, int relu)
{
    extern __shared__ char smc[];
    const uint32_t smb = (uint32_t)__cvta_generic_to_shared(smc);
    const int t = threadIdx.x, lane = t & 31, wid = t >> 5;
    const int wm = wid & 1, wn = wid >> 1;
    const int bx = blockIdx.x, by = blockIdx.y;

    float acc[4][4][4];
    #pragma unroll
    for (int a = 0; a < 4; a++)
        #pragma unroll
        for (int b = 0; b < 4; b++)
            #pragma unroll
            for (int c = 0; c < 4; c++) acc[a][b][c] = 0.f;

    const __half* P[4] = {Ah, Al, Bh, Bl};
    const int KT = K >> 5;

    auto LD = [&](int s, int k0) {
        uint32_t sb = smb + (uint32_t)s * 40960u;
        #pragma unroll
        for (int p = 0; p < 4; p++) {
            const __half* src = P[p] + (size_t)((p < 2 ? by : bx) * 128) * K + k0;
            #pragma unroll
            for (int i = 0; i < 2; i++) {
                int idx = i * 256 + t, r = idx >> 2, c = idx & 3;
                CP16(sb + (uint32_t)p * 10240u + (uint32_t)(r * 80 + c * 16),
                     src + (size_t)r * K + c * 8);
            }
        }
    };

    auto COMP = [&](int s) {
        uint32_t sb = smb + (uint32_t)s * 40960u;
        const int arow = wm * 64 + (lane & 7) + ((lane >> 3) & 1) * 8;
        const int brow = wn * 32 + (lane & 7) + ((lane >> 4) & 1) * 8;
        #pragma unroll
        for (int kk = 0; kk < 2; kk++) {
            uint32_t ah[4][4], al[4][4], bh[4][2], bl[4][2];
            const int achk = kk * 2 + (lane >> 4);
            const int bchk = kk * 2 + ((lane >> 3) & 1);
            #pragma unroll
            for (int mt = 0; mt < 4; mt++) {
                uint32_t ad = sb + (uint32_t)((arow + mt * 16) * 80 + achk * 16);
                LDSM4(ah[mt], ad);
                LDSM4(al[mt], ad + 10240u);
            }
            #pragma unroll
            for (int np = 0; np < 2; np++) {
                uint32_t bd = sb + 20480u + (uint32_t)((brow + np * 16) * 80 + bchk * 16);
                uint32_t r4[4];
                LDSM4(r4, bd);
                bh[np*2][0] = r4[0]; bh[np*2][1] = r4[1];
                bh[np*2+1][0] = r4[2]; bh[np*2+1][1] = r4[3];
                LDSM4(r4, bd + 10240u);
                bl[np*2][0] = r4[0]; bl[np*2][1] = r4[1];
                bl[np*2+1][0] = r4[2]; bl[np*2+1][1] = r4[3];
            }
            #pragma unroll
            for (int mt = 0; mt < 4; mt++)
                #pragma unroll
                for (int nt = 0; nt < 4; nt++) {
                    MMA16(acc[mt][nt], ah[mt], bh[nt]);
                    MMA16(acc[mt][nt], al[mt], bh[nt]);
                    MMA16(acc[mt][nt], ah[mt], bl[nt]);
                }
        }
    };

    LD(0, 0);
    asm volatile("cp.async.commit_group;");
    for (int kt = 0; kt < KT; kt++) {
        if (kt + 1 < KT) {
            LD((kt + 1) & 1, (kt + 1) << 5);
            asm volatile("cp.async.commit_group;");
            asm volatile("cp.async.wait_group 1;");
        } else {
            asm volatile("cp.async.wait_group 0;");
        }
        __syncthreads();
        COMP(kt & 1);
        __syncthreads();
    }

    const int lr = lane >> 2, lc = (lane & 3) * 2;
    #pragma unroll
    for (int mt = 0; mt < 4; mt++) {
        int r0 = by * 128 + wm * 64 + mt * 16 + lr;
        #pragma unroll
        for (int nt = 0; nt < 4; nt++) {
            int c0 = bx * 128 + wn * 32 + nt * 8 + lc;
            float b0 = 0.f, b1 = 0.f;
            if (bias) { float2 bv = *(const float2*)(bias + c0); b0 = bv.x; b1 = bv.y; }
            float v0 = acc[mt][nt][0] + b0, v1 = acc[mt][nt][1] + b1;
            float v2 = acc[mt][nt][2] + b0, v3 = acc[mt][nt][3] + b1;
            if (relu) { v0 = fmaxf(v0,0.f); v1 = fmaxf(v1,0.f);
                        v2 = fmaxf(v2,0.f); v3 = fmaxf(v3,0.f); }
            size_t o0 = (size_t)r0 * N + c0, o1 = (size_t)(r0 + 8) * N + c0;
            if (Cf) {
                *(float2*)(Cf + o0) = make_float2(v0, v1);
                *(float2*)(Cf + o1) = make_float2(v2, v3);
            }
            if (Ch) {
                __half2 hh, ll;
                sp2(v0, v1, &hh, &ll);
                *(__half2*)(Ch + o0) = hh; *(__half2*)(Cl + o0) = ll;
                sp2(v2, v3, &hh, &ll);
                *(__half2*)(Ch + o1) = hh; *(__half2*)(Cl + o1) = ll;
            }
        }
    }
}

// ---------------- tensor-core flash attention (fp16 split, strided) --------
#define AT_SM 184320
__global__ __launch_bounds__(256) void attn_tc(
    const __half* Qh, const __half* Ql, const __half* Kh, const __half* Kl,
    const __half* Vh, const __half* Vl, __half* Oh, __half* Ol,
    int S, int windowed, int qstr, int kstr)
{
    extern __shared__ char smc[];
    const uint32_t sb = (uint32_t)__cvta_generic_to_shared(smc);
    const int t = threadIdx.x, lane = t & 31, w = t >> 5;
    const int lr = lane >> 2, lc = lane & 3;
    const int qb = blockIdx.x, h = blockIdx.y, b = blockIdx.z;
    const size_t qbase = (size_t)(b * S + qb * 128) * qstr + h * 64;
    const size_t obase = (size_t)(b * S + qb * 128) * 1024 + h * 64;

    for (int i = t; i < 1024; i += 256) {
        int r = i >> 3, c = i & 7;
        size_t go = qbase + (size_t)r * qstr + c * 8;
        uint32_t so = (uint32_t)(r * 144 + c * 16);
        CP16(sb + so,          Qh + go);
        CP16(sb + 18432u + so, Ql + go);
    }
    asm volatile("cp.async.commit_group;");

    const int nb = windowed ? 1 : (S >> 7);
    const int jb0 = windowed ? qb : 0;

    auto ldkv = [&](int jb, int st) {
        uint32_t kb = sb + 36864u + (uint32_t)st * 73728u;
        size_t gb = (size_t)(b * S + jb * 128) * kstr + h * 64;
        for (int i = t; i < 1024; i += 256) {
            int r = i >> 3, c = i & 7;
            size_t go = gb + (size_t)r * kstr + c * 8;
            uint32_t so = (uint32_t)(r * 144 + c * 16);
            CP16(kb + so,           Kh + go);
            CP16(kb + 18432u + so,  Kl + go);
            CP16(kb + 36864u + so,  Vh + go);
            CP16(kb + 55296u + so,  Vl + go);
        }
    };

    ldkv(jb0, 0);
    asm volatile("cp.async.commit_group;");
    asm volatile("cp.async.wait_group 1;");
    __syncthreads();

    uint32_t qfh[4][4], qfl[4][4];
    {
        uint32_t qrow = (uint32_t)(w * 16 + (lane & 7) + ((lane >> 3) & 1) * 8);
        #pragma unroll
        for (int kc = 0; kc < 4; kc++) {
            uint32_t qa = sb + qrow * 144u + (uint32_t)((kc * 2 + (lane >> 4)) * 16);
            LDSM4(qfh[kc], qa);
            LDSM4(qfl[kc], qa + 18432u);
        }
    }

    float oacc[8][4];
    #pragma unroll
    for (int j = 0; j < 8; j++)
        #pragma unroll
        for (int c = 0; c < 4; c++) oacc[j][c] = 0.f;
    float m0 = -1e30f, m1 = -1e30f, l0 = 0.f, l1 = 0.f;

    for (int i = 0; i < nb; i++) {
        if (i + 1 < nb) {
            ldkv(jb0 + i + 1, (i + 1) & 1);
            asm volatile("cp.async.commit_group;");
            asm volatile("cp.async.wait_group 1;");
        } else {
            asm volatile("cp.async.wait_group 0;");
        }
        __syncthreads();
        uint32_t kb = sb + 36864u + (uint32_t)(i & 1) * 73728u;

        float sacc[16][4];
        #pragma unroll
        for (int nt = 0; nt < 16; nt++)
            #pragma unroll
            for (int c = 0; c < 4; c++) sacc[nt][c] = 0.f;

        const uint32_t krow = (uint32_t)((lane & 7) + ((lane >> 4) & 1) * 8);
        const uint32_t kchk = (uint32_t)((lane >> 3) & 1);
        #pragma unroll
        for (int np = 0; np < 8; np++) {
            #pragma unroll
            for (int kc = 0; kc < 4; kc++) {
                uint32_t ka = kb + (np * 16 + krow) * 144u + (kc * 2 + kchk) * 16u;
                uint32_t bh4[4], bl4[4];
                LDSM4(bh4, ka);
                LDSM4(bl4, ka + 18432u);
                MMA16(sacc[2*np],   qfh[kc], &bh4[0]);
                MMA16(sacc[2*np],   qfl[kc], &bh4[0]);
                MMA16(sacc[2*np],   qfh[kc], &bl4[0]);
                MMA16(sacc[2*np+1], qfh[kc], &bh4[2]);
                MMA16(sacc[2*np+1], qfl[kc], &bh4[2]);
                MMA16(sacc[2*np+1], qfh[kc], &bl4[2]);
            }
        }

        float mx0 = -1e30f, mx1 = -1e30f;
        #pragma unroll
        for (int nt = 0; nt < 16; nt++) {
            sacc[nt][0] *= 0.125f; sacc[nt][1] *= 0.125f;
            sacc[nt][2] *= 0.125f; sacc[nt][3] *= 0.125f;
            mx0 = fmaxf(mx0, fmaxf(sacc[nt][0], sacc[nt][1]));
            mx1 = fmaxf(mx1, fmaxf(sacc[nt][2], sacc[nt][3]));
        }
        mx0 = fmaxf(mx0, __shfl_xor_sync(0xffffffffu, mx0, 1));
        mx0 = fmaxf(mx0, __shfl_xor_sync(0xffffffffu, mx0, 2));
        mx1 = fmaxf(mx1, __shfl_xor_sync(0xffffffffu, mx1, 1));
        mx1 = fmaxf(mx1, __shfl_xor_sync(0xffffffffu, mx1, 2));
        float nm0 = fmaxf(m0, mx0), nm1 = fmaxf(m1, mx1);
        float cr0 = __expf(m0 - nm0), cr1 = __expf(m1 - nm1);
        l0 *= cr0; l1 *= cr1;
        #pragma unroll
        for (int j = 0; j < 8; j++) {
            oacc[j][0] *= cr0; oacc[j][1] *= cr0;
            oacc[j][2] *= cr1; oacc[j][3] *= cr1;
        }
        float rs0 = 0.f, rs1 = 0.f;
        #pragma unroll
        for (int nt = 0; nt < 16; nt++) {
            float p0 = __expf(sacc[nt][0] - nm0), p1 = __expf(sacc[nt][1] - nm0);
            float p2 = __expf(sacc[nt][2] - nm1), p3 = __expf(sacc[nt][3] - nm1);
            sacc[nt][0] = p0; sacc[nt][1] = p1; sacc[nt][2] = p2; sacc[nt][3] = p3;
            rs0 += p0 + p1; rs1 += p2 + p3;
        }
        rs0 += __shfl_xor_sync(0xffffffffu, rs0, 1);
        rs0 += __shfl_xor_sync(0xffffffffu, rs0, 2);
        rs1 += __shfl_xor_sync(0xffffffffu, rs1, 1);
        rs1 += __shfl_xor_sync(0xffffffffu, rs1, 2);
        l0 += rs0; l1 += rs1; m0 = nm0; m1 = nm1;

        const uint32_t vrow = (uint32_t)((lane & 7) + ((lane >> 3) & 1) * 8);
        const uint32_t vchk = (uint32_t)((lane >> 4) & 1);
        #pragma unroll
        for (int kc = 0; kc < 8; kc++) {
            uint32_t ph[4], pl[4];
            #pragma unroll
            for (int q = 0; q < 2; q++) {
                __half2 hh, ll;
                sp2(sacc[2*kc+q][0], sacc[2*kc+q][1], &hh, &ll);
                ph[q*2]   = *(uint32_t*)&hh; pl[q*2]   = *(uint32_t*)&ll;
                sp2(sacc[2*kc+q][2], sacc[2*kc+q][3], &hh, &ll);
                ph[q*2+1] = *(uint32_t*)&hh; pl[q*2+1] = *(uint32_t*)&ll;
            }
            #pragma unroll
            for (int p4 = 0; p4 < 4; p4++) {
                uint32_t va = kb + 36864u + (kc * 16 + vrow) * 144u + p4 * 32u + vchk * 16u;
                uint32_t vh4[4], vl4[4];
                LDSM4T(vh4, va);
                LDSM4T(vl4, va + 18432u);
                MMA16(oacc[2*p4],   ph, &vh4[0]);
                MMA16(oacc[2*p4],   pl, &vh4[0]);
                MMA16(oacc[2*p4],   ph, &vl4[0]);
                MMA16(oacc[2*p4+1], ph, &vh4[2]);
                MMA16(oacc[2*p4+1], pl, &vh4[2]);
                MMA16(oacc[2*p4+1], ph, &vl4[2]);
            }
        }
        __syncthreads();
    }

    const float i0 = 1.f / l0, i1 = 1.f / l1;
    #pragma unroll
    for (int j = 0; j < 8; j++) {
        size_t o0 = obase + (size_t)(w * 16 + lr) * 1024 + j * 8 + lc * 2;
        __half2 hh, ll;
        sp2(oacc[j][0] * i0, oacc[j][1] * i0, &hh, &ll);
        *(__half2*)(Oh + o0) = hh; *(__half2*)(Ol + o0) = ll;
        sp2(oacc[j][2] * i1, oacc[j][3] * i1, &hh, &ll);
        *(__half2*)(Oh + o0 + 8192) = hh; *(__half2*)(Ol + o0 + 8192) = ll;
    }
}

// ---------------- ln / pool / add (optional plane outputs) ----------------
__global__ __launch_bounds__(256) void ln_kernel(
    float* out, const float* in1, const float* in2, const float* g, const float* be,
    __half* ph, __half* pl)
{
    __shared__ float rs[8], rss[8];
    const int row = blockIdx.x, tid = threadIdx.x;
    const size_t base = (size_t)row * 1024 + tid * 4;
    float4 a = *(const float4*)(in1 + base), b2 = *(const float4*)(in2 + base);
    a.x += b2.x; a.y += b2.y; a.z += b2.z; a.w += b2.w;
    float s = a.x + a.y + a.z + a.w;
    float ss = a.x*a.x + a.y*a.y + a.z*a.z + a.w*a.w;
    for (int o = 16; o > 0; o >>= 1) {
        s += __shfl_xor_sync(0xffffffffu, s, o);
        ss += __shfl_xor_sync(0xffffffffu, ss, o);
    }
    if ((tid & 31) == 0) { rs[tid >> 5] = s; rss[tid >> 5] = ss; }
    __syncthreads();
    float st = 0.f, sst = 0.f;
    for (int i = 0; i < 8; i++) { st += rs[i]; sst += rss[i]; }
    const float mean = st * (1.f/1024.f), var = sst * (1.f/1024.f) - mean*mean;
    const float inv = rsqrtf(var + 1e-5f);
    float4 gg = *(const float4*)(g + tid*4), bb = *(const float4*)(be + tid*4), o4;
    o4.x = (a.x-mean)*inv*gg.x + bb.x; o4.y = (a.y-mean)*inv*gg.y + bb.y;
    o4.z = (a.z-mean)*inv*gg.z + bb.z; o4.w = (a.w-mean)*inv*gg.w + bb.w;
    *(float4*)(out + base) = o4;
    if (ph) {
        __half2 hh, ll;
        sp2(o4.x, o4.y, &hh, &ll);
        *(__half2*)(ph + base) = hh; *(__half2*)(pl + base) = ll;
        sp2(o4.z, o4.w, &hh, &ll);
        *(__half2*)(ph + base + 2) = hh; *(__half2*)(pl + base + 2) = ll;
    }
}

__global__ void poolrelu_kernel(float* out, __half* ph, __half* pl,
                                const float* in, int S2, int n4)
{
    int idx = blockIdx.x * blockDim.x + threadIdx.x;
    if (idx >= n4) return;
    int h4 = idx & 255, bt = idx >> 8, b = bt / S2, t2 = bt - b * S2;
    const float4* i0 = (const float4*)in + ((size_t)(b*S2*2 + t2*2) * 256 + h4);
    float4 a = i0[0], c = i0[256], o;
    o.x = fmaxf(fmaxf(a.x,c.x),0.f); o.y = fmaxf(fmaxf(a.y,c.y),0.f);
    o.z = fmaxf(fmaxf(a.z,c.z),0.f); o.w = fmaxf(fmaxf(a.w,c.w),0.f);
    ((float4*)out)[idx] = o;
    size_t base = (size_t)idx * 4;
    __half2 hh, ll;
    sp2(o.x, o.y, &hh, &ll);
    *(__half2*)(ph + base) = hh; *(__half2*)(pl + base) = ll;
    sp2(o.z, o.w, &hh, &ll);
    *(__half2*)(ph + base + 2) = hh; *(__half2*)(pl + base + 2) = ll;
}

__global__ void add_kernel(float* out, __half* ph, __half* pl,
                           const float* a, const float* b, int n4)
{
    int i = blockIdx.x * blockDim.x + threadIdx.x;
    if (i >= n4) return;
    float4 x = ((const float4*)a)[i], y = ((const float4*)b)[i];
    float4 o = make_float4(x.x+y.x, x.y+y.y, x.z+y.z, x.w+y.w);
    ((float4*)out)[i] = o;
    size_t base = (size_t)i * 4;
    __half2 hh, ll;
    sp2(o.x, o.y, &hh, &ll);
    *(__half2*)(ph + base) = hh; *(__half2*)(pl + base) = ll;
    sp2(o.z, o.w, &hh, &ll);
    *(__half2*)(ph + base + 2) = hh; *(__half2*)(pl + base + 2) = ll;
}

// ---------------- host ----------------
extern "C" void kernel_launch(void* const* d_in, const int* in_sizes, int n_in,
                              void* d_out, int out_size)
{
    (void)in_sizes; (void)n_in; (void)out_size;
    const float* x        = (const float*)d_in[0];
    const float* emb_w    = (const float*)d_in[1];
    const float* emb_b    = (const float*)d_in[2];
    const float* enc_qkvo = (const float*)d_in[3];
    const float* enc_ln   = (const float*)d_in[4];
    const float* ef1      = (const float*)d_in[5];
    const float* eb1      = (const float*)d_in[6];
    const float* ef2      = (const float*)d_in[7];
    const float* eb2      = (const float*)d_in[8];
    const float* conv0_w  = (const float*)d_in[9];
    const float* conv0_b  = (const float*)d_in[10];
    const float* dq0      = (const float*)d_in[11];
    const float* dln0     = (const float*)d_in[12];
    const float* da1      = (const float*)d_in[13];
    const float* da2      = (const float*)d_in[14];
    const float* dln      = (const float*)d_in[15];
    const float* df1      = (const float*)d_in[16];
    const float* db1      = (const float*)d_in[17];
    const float* df2      = (const float*)d_in[18];
    const float* db2      = (const float*)d_in[19];
    const float* ddw      = (const float*)d_in[20];
    const float* ddb      = (const float*)d_in[21];

    __half *W, *im, *As, *Zs, *at;
    float *xT, *buf;
    cudaGetSymbolAddress((void**)&W,  g_W);
    cudaGetSymbolAddress((void**)&im, g_im);
    cudaGetSymbolAddress((void**)&As, g_As);
    cudaGetSymbolAddress((void**)&Zs, g_Zs);
    cudaGetSymbolAddress((void**)&at, g_at);
    cudaGetSymbolAddress((void**)&xT, g_xT);
    cudaGetSymbolAddress((void**)&buf, g_buf);

    float *bX = buf, *bT = buf+(size_t)20*HH, *bY = buf+(size_t)24*HH,
          *bD = buf+(size_t)28*HH, *bY2 = buf+(size_t)32*HH, *bZ = buf+(size_t)36*HH;
    __half *Ash = As, *Asl = As + ASLO, *imL = im + IMLO;
    __half *Zsh = Zs, *Zsl = Zs + ZSLO;
    __half *QKVh = at, *QKVl = at + 12582912;
    __half *KVh = at + 4194304, *KVl = at + 16777216;
    __half *Ah_ = at + 25165824, *Al_ = at + 29360128;

    const size_t oE = 0, oD0 = (size_t)16*HH, oD1 = (size_t)20*HH, oD2 = (size_t)32*HH,
                 oF1e = (size_t)44*HH, oF2e = (size_t)60*HH, oF1d = (size_t)76*HH,
                 oF2d = (size_t)88*HH, oWe = (size_t)100*HH,
                 oWc = oWe + 7077888, oWd = oWc + (size_t)3*HH;
    const size_t zo[4] = {0, 4194304, 8388608, 10485760};

    float* out = (float*)d_out;
    float* Z0 = out;                      float* Z1 = out + (size_t)4194304;
    float* Z2 = out + (size_t)8388608;    float* Z3 = out + (size_t)10485760;
    float* FD0 = out + (size_t)11534336;  float* FD1 = out + (size_t)12582912;
    float* FD2 = out + (size_t)14680064;  float* FD3 = out + (size_t)18874368;

    cudaFuncSetAttribute(attn_tc, cudaFuncAttributeMaxDynamicSharedMemorySize, AT_SM);
    cudaFuncSetAttribute(gemm_fp16, cudaFuncAttributeMaxDynamicSharedMemorySize, GEMM_SM);

    dim3 b32(32, 8);
    transpose2d_kernel<<<dim3(32, 72, 4), b32>>>(xT, x, 2304, 1024);
    wsplit_kernel<<<dim3(32, 32, 16), b32>>>(W + oE,  W + WTOT + oE,  enc_qkvo, 1024, 1024);
    wsplit_kernel<<<dim3(32, 32, 4),  b32>>>(W + oD0, W + WTOT + oD0, dq0,      1024, 1024);
    wsplit_kernel<<<dim3(32, 32, 12), b32>>>(W + oD1, W + WTOT + oD1, da1,      1024, 1024);
    wsplit_kernel<<<dim3(32, 32, 12), b32>>>(W + oD2, W + WTOT + oD2, da2,      1024, 1024);
    wsplit_kernel<<<dim3(128, 32, 4), b32>>>(W + oF1e, W + WTOT + oF1e, ef1, 1024, 4096);
    wsplit_kernel<<<dim3(32, 128, 4), b32>>>(W + oF2e, W + WTOT + oF2e, ef2, 4096, 1024);
    wsplit_kernel<<<dim3(128, 32, 3), b32>>>(W + oF1d, W + WTOT + oF1d, df1, 1024, 4096);
    wsplit_kernel<<<dim3(32, 128, 3), b32>>>(W + oF2d, W + WTOT + oF2d, df2, 4096, 1024);
    convw_split_kernel<<<27648, 256>>>(W + oWe, W + WTOT + oWe, emb_w, 2304, 7077888);
    convw_split_kernel<<<12288, 256>>>(W + oWc, W + WTOT + oWc, conv0_w, 1024, 3*HH);
    deconvw_split_kernel<<<dim3(12288, 3), 256>>>(W + oWd, W + WTOT + oWd, ddw);

    auto GE = [&](const __half* ah, const __half* al, size_t ow,
                  float* Cf, __half* Ch, __half* Cl,
                  int M, int N, int K, const float* bias, int relu) {
        gemm_fp16<<<dim3(N/128, M/128), 256, GEMM_SM>>>(ah, al, W + ow, W + WTOT + ow,
                                                        Cf, Ch, Cl, M, N, K, bias, relu);
    };

    auto mhaSelf = [&](const __half* xh, const __half* xl, size_t ow, int S, int wnd) {
        int rows = 4 * S;
        GE(xh, xl, ow, nullptr, QKVh, QKVl, rows, 3072, 1024, nullptr, 0);
        attn_tc<<<dim3(S/128, 16, 4), 256, AT_SM>>>(
            QKVh, QKVl, QKVh + 1024, QKVl + 1024, QKVh + 2048, QKVl + 2048,
            Ah_, Al_, S, wnd, 3072, 3072);
        GE(Ah_, Al_, ow + (size_t)3*HH, bT, nullptr, nullptr, rows, 1024, 1024, nullptr, 0);
    };
    auto mhaCross = [&](const __half* qh, const __half* ql,
                        const __half* kvh, const __half* kvl, size_t ow, int S) {
        int rows = 4 * S;
        GE(qh, ql, ow, nullptr, QKVh, QKVl, rows, 1024, 1024, nullptr, 0);
        GE(kvh, kvl, ow + (size_t)HH, nullptr, KVh, KVl, rows, 2048, 1024, nullptr, 0);
        attn_tc<<<dim3(S/128, 16, 4), 256, AT_SM>>>(
            QKVh, QKVl, KVh, KVl, KVh + 1024, KVl + 1024,
            Ah_, Al_, S, 0, 1024, 2048);
        GE(Ah_, Al_, ow + (size_t)3*HH, bT, nullptr, nullptr, rows, 1024, 1024, nullptr, 0);
    };

    // embedding conv + relu -> bX fp32 + As planes
    im2col_split_kernel<<<(4096*6912/4 + 255)/256, 256>>>(im, imL, xT, 1024, 1024, 2304, 1, 0,
                                                          4096*6912/4);
    GE(im, imL, oWe, bX, Ash, Asl, 4096, 1024, 6912, emb_b, 1);

    const int encS[4] = {1024, 1024, 512, 256};
    float* Zp[4] = {Z0, Z1, Z2, Z3};
    for (int i = 0; i < 4; i++) {
        int S = encS[i], rows = 4 * S;
        mhaSelf(Ash, Asl, oE + (size_t)i*4*HH, S, 1);
        const float* lnb = enc_ln + (size_t)i * 4096;
        ln_kernel<<<rows, 256>>>(bY, bX, bT, lnb, lnb + 1024, Ash, Asl);
        GE(Ash, Asl, oF1e + (size_t)i*4*HH, nullptr, im, imL, rows, 4096, 1024,
           eb1 + (size_t)i*4096, 1);
        GE(im, imL, oF2e + (size_t)i*4*HH, bT, nullptr, nullptr, rows, 1024, 4096,
           eb2 + (size_t)i*1024, 0);
        ln_kernel<<<rows, 256>>>(Zp[i], bY, bT, lnb + 2048, lnb + 3072,
                                 Zsh + zo[i], Zsl + zo[i]);
        if (i == 0) {
            im2col_split_kernel<<<(rows*3072/4 + 255)/256, 256>>>(im, imL, Zp[i], S, S, 1024,
                                                                  1, 0, rows*3072/4);
            GE(im, imL, oWc, bX, Ash, Asl, rows, 1024, 3072, conv0_b, 1);
        } else if (i < 3) {
            int S2 = S/2, n4 = 4*S2*256;
            poolrelu_kernel<<<(n4 + 255)/256, 256>>>(bX, Ash, Asl, Zp[i], S2, n4);
        }
    }

    mhaSelf(Zsh + zo[3], Zsl + zo[3], oD0, 256, 0);
    ln_kernel<<<1024, 256>>>(FD0, Z3, bT, dln0, dln0 + 1024, nullptr, nullptr);

    const float* fdPrev = FD0; int Sprev = 256;
    const float* feP[3] = {Z2, Z1, Z0};
    const size_t feZ[3] = {zo[2], zo[1], zo[0]};
    const int decS[3] = {512, 1024, 1024}, decSt[3] = {2, 2, 1};
    float* fdOut[3] = {FD1, FD2, FD3};
    for (int i = 0; i < 3; i++) {
        int S = decS[i], rows = 4 * S;
        im2col_split_kernel<<<(rows*3072/4 + 255)/256, 256>>>(im, imL, fdPrev, S, Sprev, 1024,
                                                              decSt[i], 1, rows*3072/4);
        GE(im, imL, oWd + (size_t)i*3*HH, bD, Ash, Asl, rows, 1024, 3072,
           ddb + (size_t)i*1024, 1);
        const float* lnb = dln + (size_t)i * 6144;
        mhaCross(Zsh + feZ[i], Zsl + feZ[i], Ash, Asl, oD1 + (size_t)i*4*HH, S);
        ln_kernel<<<rows, 256>>>(bY, feP[i], bT, lnb, lnb + 1024, nullptr, nullptr);
        mhaCross(Ash, Asl, Zsh + feZ[i], Zsl + feZ[i], oD2 + (size_t)i*4*HH, S);
        ln_kernel<<<rows, 256>>>(bY2, bD, bT, lnb + 2048, lnb + 3072, nullptr, nullptr);
        int n4 = rows * 256;
        add_kernel<<<(n4 + 255)/256, 256>>>(bZ, Ash, Asl, bY, bY2, n4);
        GE(Ash, Asl, oF1d + (size_t)i*4*HH, nullptr, im, imL, rows, 4096, 1024,
           db1 + (size_t)i*4096, 1);
        GE(im, imL, oF2d + (size_t)i*4*HH, bT, nullptr, nullptr, rows, 1024, 4096,
           db2 + (size_t)i*1024, 0);
        ln_kernel<<<rows, 256>>>(fdOut[i], bZ, bT, lnb + 4096, lnb + 5120, nullptr, nullptr);
        fdPrev = fdOut[i]; Sprev = S;
    }
}

// round 10
// speedup vs baseline: 2.5706x; 1.0236x over previous
#include <cuda_runtime.h>
#include <cuda_fp16.h>
#include <cstdint>
#include <cstddef>

#define HH (1024*1024)
#define WTOT ((size_t)124518400)
#define IMLO ((size_t)28311552)
#define ASLO ((size_t)16777216)
#define ZSLO ((size_t)11534336)

__device__ __half g_W [(size_t)2*WTOT];
__device__ __half g_im[(size_t)2*28311552];
__device__ __half g_As[(size_t)2*16777216];
__device__ __half g_Zs[(size_t)2*11534336];
__device__ __half g_at[(size_t)64*HH];
__device__ float  g_xT[(size_t)9437184];
__device__ float  g_buf[(size_t)56*HH];

__device__ __forceinline__ void sp2(float a, float b, __half2* hi, __half2* lo)
{
    __half2 h = __floats2half2_rn(a, b);
    float2 f = __half22float2(h);
    *hi = h;
    *lo = __floats2half2_rn(a - f.x, b - f.y);
}

// ---------------- prep kernels ----------------
__global__ void transpose2d_kernel(float* dst, const float* src, int R, int C)
{
    __shared__ float tile[32][33];
    int b = blockIdx.z;
    const float* s = src + (size_t)b * R * C;
    float* d = dst + (size_t)b * R * C;
    int c0 = blockIdx.x * 32, r0 = blockIdx.y * 32, tx = threadIdx.x, ty = threadIdx.y;
    for (int i = 0; i < 32; i += 8) tile[ty + i][tx] = s[(size_t)(r0 + ty + i) * C + c0 + tx];
    __syncthreads();
    for (int i = 0; i < 32; i += 8) d[(size_t)(c0 + ty + i) * R + r0 + tx] = tile[tx][ty + i];
}

__global__ void wsplit_kernel(__half* hi, __half* lo, const float* src, int K, int N)
{
    __shared__ float tile[32][33];
    size_t mo = (size_t)blockIdx.z * K * N;
    int n0 = blockIdx.x * 32, k0 = blockIdx.y * 32, tx = threadIdx.x, ty = threadIdx.y;
    for (int i = 0; i < 32; i += 8) tile[ty + i][tx] = src[mo + (size_t)(k0 + ty + i) * N + n0 + tx];
    __syncthreads();
    for (int i = 0; i < 32; i += 8) {
        float x = tile[tx][ty + i];
        __half h = __float2half_rn(x);
        size_t o = mo + (size_t)(n0 + ty + i) * K + k0 + tx;
        hi[o] = h; lo[o] = __float2half_rn(x - __half2float(h));
    }
}

__global__ void convw_split_kernel(__half* hi, __half* lo, const float* src, int Cin, int total)
{
    int idx = blockIdx.x * 256 + threadIdx.x;
    if (idx >= total) return;
    int K = 3 * Cin;
    int n = idx / K, r = idx - n * K;
    int ks = r / Cin, c = r - ks * Cin;
    float x = src[((size_t)n * Cin + c) * 3 + ks];
    __half h = __float2half_rn(x);
    hi[idx] = h; lo[idx] = __float2half_rn(x - __half2float(h));
}

__global__ void deconvw_split_kernel(__half* hi, __half* lo, const float* src)
{
    int idx = blockIdx.x * 256 + threadIdx.x;
    int i = blockIdx.y;
    int o = idx / 3072, r = idx - o * 3072;
    int ks = r >> 10, c = r & 1023;
    float x = src[(size_t)i * 3 * HH + ((size_t)c * 1024 + o) * 3 + ks];
    __half h = __float2half_rn(x);
    size_t d = (size_t)i * 3 * HH + idx;
    hi[d] = h; lo[d] = __float2half_rn(x - __half2float(h));
}

__global__ void im2col_split_kernel(__half* hi, __half* lo, const float* In,
                                    int Tout, int Tin, int Cin, int stride, int mode, int total4)
{
    int idx = blockIdx.x * 256 + threadIdx.x;
    if (idx >= total4) return;
    int kw = 3 * Cin / 4, cq4 = Cin / 4;
    int kq = idx % kw, m = idx / kw;
    int ks = kq / cq4, c4 = kq - ks * cq4;
    int b = m / Tout, tt = m - b * Tout;
    float4 v = make_float4(0.f, 0.f, 0.f, 0.f);
    int tin = -1;
    if (mode == 0) { int ti = tt + ks - 1; if (ti >= 0 && ti < Tin) tin = ti; }
    else { int num = tt + 1 - ks;
           if (num >= 0 && num % stride == 0) { int ti = num / stride; if (ti < Tin) tin = ti; } }
    if (tin >= 0) v = *(const float4*)(In + ((size_t)(b * Tin + tin) * Cin + c4 * 4));
    __half2 h01, l01, h23, l23;
    sp2(v.x, v.y, &h01, &l01);
    sp2(v.z, v.w, &h23, &l23);
    *(__half2*)(hi + 4*(size_t)idx)     = h01;
    *(__half2*)(hi + 4*(size_t)idx + 2) = h23;
    *(__half2*)(lo + 4*(size_t)idx)     = l01;
    *(__half2*)(lo + 4*(size_t)idx + 2) = l23;
}

// ---------------- MMA macros ----------------
#define GEMM_SM 81920
#define CP16(d, s) asm volatile("cp.async.ca.shared.global [%0], [%1], 16;" :: "r"(d), "l"(s))
#define LDSM4(r, a) asm volatile( \
    "ldmatrix.sync.aligned.m8n8.x4.shared.b16 {%0,%1,%2,%3}, [%4];" \
    : "=r"((r)[0]), "=r"((r)[1]), "=r"((r)[2]), "=r"((r)[3]) : "r"(a))
#define LDSM4T(r, a) asm volatile( \
    "ldmatrix.sync.aligned.m8n8.x4.trans.shared.b16 {%0,%1,%2,%3}, [%4];" \
    : "=r"((r)[0]), "=r"((r)[1]), "=r"((r)[2]), "=r"((r)[3]) : "r"(a))
#define MMA16(d, A_, B_) asm volatile( \
    "mma.sync.aligned.m16n8k16.row.col.f32.f16.f16.f32 " \
    "{%0,%1,%2,%3},{%4,%5,%6,%7},{%8,%9},{%0,%1,%2,%3};" \
    : "+f"((d)[0]), "+f"((d)[1]), "+f"((d)[2]), "+f"((d)[3]) \
    : "r"((A_)[0]), "r"((A_)[1]), "r"((A_)[2]), "r"((A_)[3]), "r"((B_)[0]), "r"((B_)[1]))

// ---------------- fp16x2-split tensor GEMM body ----------------
__device__ __forceinline__ void gemm_body(
    const __half* Ah, const __half* Al, const __half* Bh, const __half* Bl,
    float* Cf, __half* Ch, __half* Cl,
    int M, int N, int K, const float* bias, int relu)
{
    extern __shared__ char smc[];
    const uint32_t smb = (uint32_t)__cvta_generic_to_shared(smc);
    const int t = threadIdx.x, lane = t & 31, wid = t >> 5;
    const int wm = wid & 1, wn = wid >> 1;
    const int bx = blockIdx.x, by = blockIdx.y;

    float acc[4][4][4];
    #pragma unroll
    for (int a = 0; a < 4; a++)
        #pragma unroll
        for (int b = 0; b < 4; b++)
            #pragma unroll
            for (int c = 0; c < 4; c++) acc[a][b][c] = 0.f;

    const __half* P[4] = {Ah, Al, Bh, Bl};
    const int KT = K >> 5;

    auto LD = [&](int s, int k0) {
        uint32_t sb = smb + (uint32_t)s * 40960u;
        #pragma unroll
        for (int p = 0; p < 4; p++) {
            const __half* src = P[p] + (size_t)((p < 2 ? by : bx) * 128) * K + k0;
            #pragma unroll
            for (int i = 0; i < 2; i++) {
                int idx = i * 256 + t, r = idx >> 2, c = idx & 3;
                CP16(sb + (uint32_t)p * 10240u + (uint32_t)(r * 80 + c * 16),
                     src + (size_t)r * K + c * 8);
            }
        }
    };

    auto COMP = [&](int s) {
        uint32_t sb = smb + (uint32_t)s * 40960u;
        const int arow = wm * 64 + (lane & 7) + ((lane >> 3) & 1) * 8;
        const int brow = wn * 32 + (lane & 7) + ((lane >> 4) & 1) * 8;
        #pragma unroll
        for (int kk = 0; kk < 2; kk++) {
            uint32_t ah[4][4], al[4][4], bh[4][2], bl[4][2];
            const int achk = kk * 2 + (lane >> 4);
            const int bchk = kk * 2 + ((lane >> 3) & 1);
            #pragma unroll
            for (int mt = 0; mt < 4; mt++) {
                uint32_t ad = sb + (uint32_t)((arow + mt * 16) * 80 + achk * 16);
                LDSM4(ah[mt], ad);
                LDSM4(al[mt], ad + 10240u);
            }
            #pragma unroll
            for (int np = 0; np < 2; np++) {
                uint32_t bd = sb + 20480u + (uint32_t)((brow + np * 16) * 80 + bchk * 16);
                uint32_t r4[4];
                LDSM4(r4, bd);
                bh[np*2][0] = r4[0]; bh[np*2][1] = r4[1];
                bh[np*2+1][0] = r4[2]; bh[np*2+1][1] = r4[3];
                LDSM4(r4, bd + 10240u);
                bl[np*2][0] = r4[0]; bl[np*2][1] = r4[1];
                bl[np*2+1][0] = r4[2]; bl[np*2+1][1] = r4[3];
            }
            #pragma unroll
            for (int mt = 0; mt < 4; mt++)
                #pragma unroll
                for (int nt = 0; nt < 4; nt++) {
                    MMA16(acc[mt][nt], ah[mt], bh[nt]);
                    MMA16(acc[mt][nt], al[mt], bh[nt]);
                    MMA16(acc[mt][nt], ah[mt], bl[nt]);
                }
        }
    };

    LD(0, 0);
    asm volatile("cp.async.commit_group;");
    for (int kt = 0; kt < KT; kt++) {
        if (kt + 1 < KT) {
            LD((kt + 1) & 1, (kt + 1) << 5);
            asm volatile("cp.async.commit_group;");
            asm volatile("cp.async.wait_group 1;");
        } else {
            asm volatile("cp.async.wait_group 0;");
        }
        __syncthreads();
        COMP(kt & 1);
        __syncthreads();
    }

    const int lr = lane >> 2, lc = (lane & 3) * 2;
    #pragma unroll
    for (int mt = 0; mt < 4; mt++) {
        int r0 = by * 128 + wm * 64 + mt * 16 + lr;
        #pragma unroll
        for (int nt = 0; nt < 4; nt++) {
            int c0 = bx * 128 + wn * 32 + nt * 8 + lc;
            float b0 = 0.f, b1 = 0.f;
            if (bias) { float2 bv = *(const float2*)(bias + c0); b0 = bv.x; b1 = bv.y; }
            float v0 = acc[mt][nt][0] + b0, v1 = acc[mt][nt][1] + b1;
            float v2 = acc[mt][nt][2] + b0, v3 = acc[mt][nt][3] + b1;
            if (relu) { v0 = fmaxf(v0,0.f); v1 = fmaxf(v1,0.f);
                        v2 = fmaxf(v2,0.f); v3 = fmaxf(v3,0.f); }
            size_t o0 = (size_t)r0 * N + c0, o1 = (size_t)(r0 + 8) * N + c0;
            if (Cf) {
                *(float2*)(Cf + o0) = make_float2(v0, v1);
                *(float2*)(Cf + o1) = make_float2(v2, v3);
            }
            if (Ch) {
                __half2 hh, ll;
                sp2(v0, v1, &hh, &ll);
                *(__half2*)(Ch + o0) = hh; *(__half2*)(Cl + o0) = ll;
                sp2(v2, v3, &hh, &ll);
                *(__half2*)(Ch + o1) = hh; *(__half2*)(Cl + o1) = ll;
            }
        }
    }
}

__global__ __launch_bounds__(256) void gemm_fp16(
    const __half* Ah, const __half* Al, const __half* Bh, const __half* Bl,
    float* Cf, __half* Ch, __half* Cl,
    int M, int N, int K, const float* bias, int relu)
{
    gemm_body(Ah, Al, Bh, Bl, Cf, Ch, Cl, M, N, K, bias, relu);
}

__global__ __launch_bounds__(256) void gemm_dual(
    const __half* A0h, const __half* A0l, const __half* B0h, const __half* B0l,
    float* C0f, __half* C0h, __half* C0l,
    const __half* A1h, const __half* A1l, const __half* B1h, const __half* B1l,
    float* C1f, __half* C1h, __half* C1l,
    int M, int N, int K)
{
    if (blockIdx.z == 0)
        gemm_body(A0h, A0l, B0h, B0l, C0f, C0h, C0l, M, N, K, nullptr, 0);
    else
        gemm_body(A1h, A1l, B1h, B1l, C1f, C1h, C1l, M, N, K, nullptr, 0);
}

// ---------------- flash attention body (fp16 split, strided) --------
#define AT_SM 184320
__device__ __forceinline__ void attn_body(
    const __half* Qh, const __half* Ql, const __half* Kh, const __half* Kl,
    const __half* Vh, const __half* Vl, __half* Oh, __half* Ol,
    int S, int windowed, int qstr, int kstr, int qb, int h, int b)
{
    extern __shared__ char smc[];
    const uint32_t sb = (uint32_t)__cvta_generic_to_shared(smc);
    const int t = threadIdx.x, lane = t & 31, w = t >> 5;
    const int lr = lane >> 2, lc = lane & 3;
    const size_t qbase = (size_t)(b * S + qb * 128) * qstr + h * 64;
    const size_t obase = (size_t)(b * S + qb * 128) * 1024 + h * 64;

    for (int i = t; i < 1024; i += 256) {
        int r = i >> 3, c = i & 7;
        size_t go = qbase + (size_t)r * qstr + c * 8;
        uint32_t so = (uint32_t)(r * 144 + c * 16);
        CP16(sb + so,          Qh + go);
        CP16(sb + 18432u + so, Ql + go);
    }
    asm volatile("cp.async.commit_group;");

    const int nb = windowed ? 1 : (S >> 7);
    const int jb0 = windowed ? qb : 0;

    auto ldkv = [&](int jb, int st) {
        uint32_t kb = sb + 36864u + (uint32_t)st * 73728u;
        size_t gb = (size_t)(b * S + jb * 128) * kstr + h * 64;
        for (int i = t; i < 1024; i += 256) {
            int r = i >> 3, c = i & 7;
            size_t go = gb + (size_t)r * kstr + c * 8;
            uint32_t so = (uint32_t)(r * 144 + c * 16);
            CP16(kb + so,           Kh + go);
            CP16(kb + 18432u + so,  Kl + go);
            CP16(kb + 36864u + so,  Vh + go);
            CP16(kb + 55296u + so,  Vl + go);
        }
    };

    ldkv(jb0, 0);
    asm volatile("cp.async.commit_group;");
    asm volatile("cp.async.wait_group 1;");
    __syncthreads();

    uint32_t qfh[4][4], qfl[4][4];
    {
        uint32_t qrow = (uint32_t)(w * 16 + (lane & 7) + ((lane >> 3) & 1) * 8);
        #pragma unroll
        for (int kc = 0; kc < 4; kc++) {
            uint32_t qa = sb + qrow * 144u + (uint32_t)((kc * 2 + (lane >> 4)) * 16);
            LDSM4(qfh[kc], qa);
            LDSM4(qfl[kc], qa + 18432u);
        }
    }

    float oacc[8][4];
    #pragma unroll
    for (int j = 0; j < 8; j++)
        #pragma unroll
        for (int c = 0; c < 4; c++) oacc[j][c] = 0.f;
    float m0 = -1e30f, m1 = -1e30f, l0 = 0.f, l1 = 0.f;

    for (int i = 0; i < nb; i++) {
        if (i + 1 < nb) {
            ldkv(jb0 + i + 1, (i + 1) & 1);
            asm volatile("cp.async.commit_group;");
            asm volatile("cp.async.wait_group 1;");
        } else {
            asm volatile("cp.async.wait_group 0;");
        }
        __syncthreads();
        uint32_t kb = sb + 36864u + (uint32_t)(i & 1) * 73728u;

        float sacc[16][4];
        #pragma unroll
        for (int nt = 0; nt < 16; nt++)
            #pragma unroll
            for (int c = 0; c < 4; c++) sacc[nt][c] = 0.f;

        const uint32_t krow = (uint32_t)((lane & 7) + ((lane >> 4) & 1) * 8);
        const uint32_t kchk = (uint32_t)((lane >> 3) & 1);
        #pragma unroll
        for (int np = 0; np < 8; np++) {
            #pragma unroll
            for (int kc = 0; kc < 4; kc++) {
                uint32_t ka = kb + (np * 16 + krow) * 144u + (kc * 2 + kchk) * 16u;
                uint32_t bh4[4], bl4[4];
                LDSM4(bh4, ka);
                LDSM4(bl4, ka + 18432u);
                MMA16(sacc[2*np],   qfh[kc], &bh4[0]);
                MMA16(sacc[2*np],   qfl[kc], &bh4[0]);
                MMA16(sacc[2*np],   qfh[kc], &bl4[0]);
                MMA16(sacc[2*np+1], qfh[kc], &bh4[2]);
                MMA16(sacc[2*np+1], qfl[kc], &bh4[2]);
                MMA16(sacc[2*np+1], qfh[kc], &bl4[2]);
            }
        }

        float mx0 = -1e30f, mx1 = -1e30f;
        #pragma unroll
        for (int nt = 0; nt < 16; nt++) {
            sacc[nt][0] *= 0.125f; sacc[nt][1] *= 0.125f;
            sacc[nt][2] *= 0.125f; sacc[nt][3] *= 0.125f;
            mx0 = fmaxf(mx0, fmaxf(sacc[nt][0], sacc[nt][1]));
            mx1 = fmaxf(mx1, fmaxf(sacc[nt][2], sacc[nt][3]));
        }
        mx0 = fmaxf(mx0, __shfl_xor_sync(0xffffffffu, mx0, 1));
        mx0 = fmaxf(mx0, __shfl_xor_sync(0xffffffffu, mx0, 2));
        mx1 = fmaxf(mx1, __shfl_xor_sync(0xffffffffu, mx1, 1));
        mx1 = fmaxf(mx1, __shfl_xor_sync(0xffffffffu, mx1, 2));
        float nm0 = fmaxf(m0, mx0), nm1 = fmaxf(m1, mx1);
        float cr0 = __expf(m0 - nm0), cr1 = __expf(m1 - nm1);
        l0 *= cr0; l1 *= cr1;
        #pragma unroll
        for (int j = 0; j < 8; j++) {
            oacc[j][0] *= cr0; oacc[j][1] *= cr0;
            oacc[j][2] *= cr1; oacc[j][3] *= cr1;
        }
        float rs0 = 0.f, rs1 = 0.f;
        #pragma unroll
        for (int nt = 0; nt < 16; nt++) {
            float p0 = __expf(sacc[nt][0] - nm0), p1 = __expf(sacc[nt][1] - nm0);
            float p2 = __expf(sacc[nt][2] - nm1), p3 = __expf(sacc[nt][3] - nm1);
            sacc[nt][0] = p0; sacc[nt][1] = p1; sacc[nt][2] = p2; sacc[nt][3] = p3;
            rs0 += p0 + p1; rs1 += p2 + p3;
        }
        rs0 += __shfl_xor_sync(0xffffffffu, rs0, 1);
        rs0 += __shfl_xor_sync(0xffffffffu, rs0, 2);
        rs1 += __shfl_xor_sync(0xffffffffu, rs1, 1);
        rs1 += __shfl_xor_sync(0xffffffffu, rs1, 2);
        l0 += rs0; l1 += rs1; m0 = nm0; m1 = nm1;

        const uint32_t vrow = (uint32_t)((lane & 7) + ((lane >> 3) & 1) * 8);
        const uint32_t vchk = (uint32_t)((lane >> 4) & 1);
        #pragma unroll
        for (int kc = 0; kc < 8; kc++) {
            uint32_t ph[4], pl[4];
            #pragma unroll
            for (int q = 0; q < 2; q++) {
                __half2 hh, ll;
                sp2(sacc[2*kc+q][0], sacc[2*kc+q][1], &hh, &ll);
                ph[q*2]   = *(uint32_t*)&hh; pl[q*2]   = *(uint32_t*)&ll;
                sp2(sacc[2*kc+q][2], sacc[2*kc+q][3], &hh, &ll);
                ph[q*2+1] = *(uint32_t*)&hh; pl[q*2+1] = *(uint32_t*)&ll;
            }
            #pragma unroll
            for (int p4 = 0; p4 < 4; p4++) {
                uint32_t va = kb + 36864u + (kc * 16 + vrow) * 144u + p4 * 32u + vchk * 16u;
                uint32_t vh4[4], vl4[4];
                LDSM4T(vh4, va);
                LDSM4T(vl4, va + 18432u);
                MMA16(oacc[2*p4],   ph, &vh4[0]);
                MMA16(oacc[2*p4],   pl, &vh4[0]);
                MMA16(oacc[2*p4],   ph, &vl4[0]);
                MMA16(oacc[2*p4+1], ph, &vh4[2]);
                MMA16(oacc[2*p4+1], pl, &vh4[2]);
                MMA16(oacc[2*p4+1], ph, &vl4[2]);
            }
        }
        __syncthreads();
    }

    const float i0 = 1.f / l0, i1 = 1.f / l1;
    #pragma unroll
    for (int j = 0; j < 8; j++) {
        size_t o0 = obase + (size_t)(w * 16 + lr) * 1024 + j * 8 + lc * 2;
        __half2 hh, ll;
        sp2(oacc[j][0] * i0, oacc[j][1] * i0, &hh, &ll);
        *(__half2*)(Oh + o0) = hh; *(__half2*)(Ol + o0) = ll;
        sp2(oacc[j][2] * i1, oacc[j][3] * i1, &hh, &ll);
        *(__half2*)(Oh + o0 + 8192) = hh; *(__half2*)(Ol + o0 + 8192) = ll;
    }
}

__global__ __launch_bounds__(256) void attn_tc(
    const __half* Qh, const __half* Ql, const __half* Kh, const __half* Kl,
    const __half* Vh, const __half* Vl, __half* Oh, __half* Ol,
    int S, int windowed, int qstr, int kstr)
{
    attn_body(Qh, Ql, Kh, Kl, Vh, Vl, Oh, Ol, S, windowed, qstr, kstr,
              blockIdx.x, blockIdx.y, blockIdx.z);
}

__global__ __launch_bounds__(256) void attn_tc_dual(
    const __half* Q0h, const __half* Q0l, const __half* K0h, const __half* K0l,
    const __half* V0h, const __half* V0l, __half* O0h, __half* O0l,
    const __half* Q1h, const __half* Q1l, const __half* K1h, const __half* K1l,
    const __half* V1h, const __half* V1l, __half* O1h, __half* O1l,
    int S)
{
    int b = blockIdx.z & 3;
    if ((blockIdx.z >> 2) == 0)
        attn_body(Q0h, Q0l, K0h, K0l, V0h, V0l, O0h, O0l, S, 0, 1024, 2048,
                  blockIdx.x, blockIdx.y, b);
    else
        attn_body(Q1h, Q1l, K1h, K1l, V1h, V1l, O1h, O1l, S, 0, 1024, 2048,
                  blockIdx.x, blockIdx.y, b);
}

// ---------------- ln / pool / add ----------------
__device__ __forceinline__ void ln_body(
    float* out, const float* in1, const float* in2, const float* g, const float* be,
    __half* ph, __half* pl, int row)
{
    __shared__ float rs[8], rss[8];
    const int tid = threadIdx.x;
    const size_t base = (size_t)row * 1024 + tid * 4;
    float4 a = *(const float4*)(in1 + base), b2 = *(const float4*)(in2 + base);
    a.x += b2.x; a.y += b2.y; a.z += b2.z; a.w += b2.w;
    float s = a.x + a.y + a.z + a.w;
    float ss = a.x*a.x + a.y*a.y + a.z*a.z + a.w*a.w;
    for (int o = 16; o > 0; o >>= 1) {
        s += __shfl_xor_sync(0xffffffffu, s, o);
        ss += __shfl_xor_sync(0xffffffffu, ss, o);
    }
    if ((tid & 31) == 0) { rs[tid >> 5] = s; rss[tid >> 5] = ss; }
    __syncthreads();
    float st = 0.f, sst = 0.f;
    for (int i = 0; i < 8; i++) { st += rs[i]; sst += rss[i]; }
    const float mean = st * (1.f/1024.f), var = sst * (1.f/1024.f) - mean*mean;
    const float inv = rsqrtf(var + 1e-5f);
    float4 gg = *(const float4*)(g + tid*4), bb = *(const float4*)(be + tid*4), o4;
    o4.x = (a.x-mean)*inv*gg.x + bb.x; o4.y = (a.y-mean)*inv*gg.y + bb.y;
    o4.z = (a.z-mean)*inv*gg.z + bb.z; o4.w = (a.w-mean)*inv*gg.w + bb.w;
    *(float4*)(out + base) = o4;
    if (ph) {
        __half2 hh, ll;
        sp2(o4.x, o4.y, &hh, &ll);
        *(__half2*)(ph + base) = hh; *(__half2*)(pl + base) = ll;
        sp2(o4.z, o4.w, &hh, &ll);
        *(__half2*)(ph + base + 2) = hh; *(__half2*)(pl + base + 2) = ll;
    }
}

__global__ __launch_bounds__(256) void ln_kernel(
    float* out, const float* in1, const float* in2, const float* g, const float* be,
    __half* ph, __half* pl)
{
    ln_body(out, in1, in2, g, be, ph, pl, blockIdx.x);
}

__global__ __launch_bounds__(256) void ln_dual(
    float* o0, const float* a0, const float* b0, const float* g0, const float* e0,
    float* o1, const float* a1, const float* b1, const float* g1, const float* e1)
{
    if (blockIdx.y == 0) ln_body(o0, a0, b0, g0, e0, nullptr, nullptr, blockIdx.x);
    else                 ln_body(o1, a1, b1, g1, e1, nullptr, nullptr, blockIdx.x);
}

__global__ void poolrelu_kernel(float* out, __half* ph, __half* pl,
                                const float* in, int S2, int n4)
{
    int idx = blockIdx.x * blockDim.x + threadIdx.x;
    if (idx >= n4) return;
    int h4 = idx & 255, bt = idx >> 8, b = bt / S2, t2 = bt - b * S2;
    const float4* i0 = (const float4*)in + ((size_t)(b*S2*2 + t2*2) * 256 + h4);
    float4 a = i0[0], c = i0[256], o;
    o.x = fmaxf(fmaxf(a.x,c.x),0.f); o.y = fmaxf(fmaxf(a.y,c.y),0.f);
    o.z = fmaxf(fmaxf(a.z,c.z),0.f); o.w = fmaxf(fmaxf(a.w,c.w),0.f);
    ((float4*)out)[idx] = o;
    size_t base = (size_t)idx * 4;
    __half2 hh, ll;
    sp2(o.x, o.y, &hh, &ll);
    *(__half2*)(ph + base) = hh; *(__half2*)(pl + base) = ll;
    sp2(o.z, o.w, &hh, &ll);
    *(__half2*)(ph + base + 2) = hh; *(__half2*)(pl + base + 2) = ll;
}

__global__ void add_kernel(float* out, __half* ph, __half* pl,
                           const float* a, const float* b, int n4)
{
    int i = blockIdx.x * blockDim.x + threadIdx.x;
    if (i >= n4) return;
    float4 x = ((const float4*)a)[i], y = ((const float4*)b)[i];
    float4 o = make_float4(x.x+y.x, x.y+y.y, x.z+y.z, x.w+y.w);
    ((float4*)out)[i] = o;
    size_t base = (size_t)i * 4;
    __half2 hh, ll;
    sp2(o.x, o.y, &hh, &ll);
    *(__half2*)(ph + base) = hh; *(__half2*)(pl + base) = ll;
    sp2(o.z, o.w, &hh, &ll);
    *(__half2*)(ph + base + 2) = hh; *(__half2*)(pl + base + 2) = ll;
}

// ---------------- host ----------------
extern "C" void kernel_launch(void* const* d_in, const int* in_sizes, int n_in,
                              void* d_out, int out_size)
{
    (void)in_sizes; (void)n_in; (void)out_size;
    const float* x        = (const float*)d_in[0];
    const float* emb_w    = (const float*)d_in[1];
    const float* emb_b    = (const float*)d_in[2];
    const float* enc_qkvo = (const float*)d_in[3];
    const float* enc_ln   = (const float*)d_in[4];
    const float* ef1      = (const float*)d_in[5];
    const float* eb1      = (const float*)d_in[6];
    const float* ef2      = (const float*)d_in[7];
    const float* eb2      = (const float*)d_in[8];
    const float* conv0_w  = (const float*)d_in[9];
    const float* conv0_b  = (const float*)d_in[10];
    const float* dq0      = (const float*)d_in[11];
    const float* dln0     = (const float*)d_in[12];
    const float* da1      = (const float*)d_in[13];
    const float* da2      = (const float*)d_in[14];
    const float* dln      = (const float*)d_in[15];
    const float* df1      = (const float*)d_in[16];
    const float* db1      = (const float*)d_in[17];
    const float* df2      = (const float*)d_in[18];
    const float* db2      = (const float*)d_in[19];
    const float* ddw      = (const float*)d_in[20];
    const float* ddb      = (const float*)d_in[21];

    __half *W, *im, *As, *Zs, *at;
    float *xT, *buf;
    cudaGetSymbolAddress((void**)&W,  g_W);
    cudaGetSymbolAddress((void**)&im, g_im);
    cudaGetSymbolAddress((void**)&As, g_As);
    cudaGetSymbolAddress((void**)&Zs, g_Zs);
    cudaGetSymbolAddress((void**)&at, g_at);
    cudaGetSymbolAddress((void**)&xT, g_xT);
    cudaGetSymbolAddress((void**)&buf, g_buf);

    float *bX = buf, *bT = buf+(size_t)20*HH, *bY = buf+(size_t)24*HH,
          *bD = buf+(size_t)28*HH, *bY2 = buf+(size_t)32*HH, *bZ = buf+(size_t)36*HH,
          *bT2 = buf+(size_t)40*HH;
    __half *Ash = As, *Asl = As + ASLO, *imL = im + IMLO;
    __half *Zsh = Zs, *Zsl = Zs + ZSLO;
    // attention scratch layout (halfs)
    __half *Q0h = at,                 *Q0l = at + (size_t)4*HH,
           *KV0h = at + (size_t)8*HH,  *KV0l = at + (size_t)16*HH,
           *A0h = at + (size_t)24*HH,  *A0l = at + (size_t)28*HH,
           *Q1h = at + (size_t)32*HH,  *Q1l = at + (size_t)36*HH,
           *KV1h = at + (size_t)40*HH, *KV1l = at + (size_t)48*HH,
           *A1h = at + (size_t)56*HH,  *A1l = at + (size_t)60*HH;
    __half *QKVh = at, *QKVl = at + (size_t)12*HH;   // self-attn fused (rows x 3072)

    const size_t oE = 0, oD0 = (size_t)16*HH, oD1 = (size_t)20*HH, oD2 = (size_t)32*HH,
                 oF1e = (size_t)44*HH, oF2e = (size_t)60*HH, oF1d = (size_t)76*HH,
                 oF2d = (size_t)88*HH, oWe = (size_t)100*HH,
                 oWc = oWe + 7077888, oWd = oWc + (size_t)3*HH;
    const size_t zo[4] = {0, 4194304, 8388608, 10485760};

    float* out = (float*)d_out;
    float* Z0 = out;                      float* Z1 = out + (size_t)4194304;
    float* Z2 = out + (size_t)8388608;    float* Z3 = out + (size_t)10485760;
    float* FD0 = out + (size_t)11534336;  float* FD1 = out + (size_t)12582912;
    float* FD2 = out + (size_t)14680064;  float* FD3 = out + (size_t)18874368;

    cudaFuncSetAttribute(attn_tc, cudaFuncAttributeMaxDynamicSharedMemorySize, AT_SM);
    cudaFuncSetAttribute(attn_tc_dual, cudaFuncAttributeMaxDynamicSharedMemorySize, AT_SM);
    cudaFuncSetAttribute(gemm_fp16, cudaFuncAttributeMaxDynamicSharedMemorySize, GEMM_SM);
    cudaFuncSetAttribute(gemm_dual, cudaFuncAttributeMaxDynamicSharedMemorySize, GEMM_SM);

    auto GE = [&](const __half* ah, const __half* al, size_t ow,
                  float* Cf, __half* Ch, __half* Cl,
                  int M, int N, int K, const float* bias, int relu) {
        gemm_fp16<<<dim3(N/128, M/128), 256, GEMM_SM>>>(ah, al, W + ow, W + WTOT + ow,
                                                        Cf, Ch, Cl, M, N, K, bias, relu);
    };
    auto GE2 = [&](const __half* a0h, const __half* a0l, size_t w0,
                   float* c0f, __half* c0h, __half* c0l,
                   const __half* a1h, const __half* a1l, size_t w1,
                   float* c1f, __half* c1h, __half* c1l,
                   int M, int N, int K) {
        gemm_dual<<<dim3(N/128, M/128, 2), 256, GEMM_SM>>>(
            a0h, a0l, W + w0, W + WTOT + w0, c0f, c0h, c0l,
            a1h, a1l, W + w1, W + WTOT + w1, c1f, c1h, c1l, M, N, K);
    };

    // ---- prep (ordered so launch index 5 is the embedding GEMM for ncu) ----
    dim3 b32(32, 8);
    transpose2d_kernel<<<dim3(32, 72, 4), b32>>>(xT, x, 2304, 1024);                      // 0
    convw_split_kernel<<<27648, 256>>>(W + oWe, W + WTOT + oWe, emb_w, 2304, 7077888);    // 1
    im2col_split_kernel<<<(4096*6912/4 + 255)/256, 256>>>(im, imL, xT, 1024, 1024, 2304,  // 2
                                                          1, 0, 4096*6912/4);
    wsplit_kernel<<<dim3(32, 32, 16), b32>>>(W + oE,  W + WTOT + oE,  enc_qkvo, 1024, 1024); // 3
    wsplit_kernel<<<dim3(32, 32, 4),  b32>>>(W + oD0, W + WTOT + oD0, dq0, 1024, 1024);      // 4
    GE(im, imL, oWe, bX, Ash, Asl, 4096, 1024, 6912, emb_b, 1);                              // 5 <- profiled
    wsplit_kernel<<<dim3(32, 32, 12), b32>>>(W + oD1, W + WTOT + oD1, da1, 1024, 1024);
    wsplit_kernel<<<dim3(32, 32, 12), b32>>>(W + oD2, W + WTOT + oD2, da2, 1024, 1024);
    wsplit_kernel<<<dim3(128, 32, 4), b32>>>(W + oF1e, W + WTOT + oF1e, ef1, 1024, 4096);
    wsplit_kernel<<<dim3(32, 128, 4), b32>>>(W + oF2e, W + WTOT + oF2e, ef2, 4096, 1024);
    wsplit_kernel<<<dim3(128, 32, 3), b32>>>(W + oF1d, W + WTOT + oF1d, df1, 1024, 4096);
    wsplit_kernel<<<dim3(32, 128, 3), b32>>>(W + oF2d, W + WTOT + oF2d, df2, 4096, 1024);
    convw_split_kernel<<<12288, 256>>>(W + oWc, W + WTOT + oWc, conv0_w, 1024, 3*HH);
    deconvw_split_kernel<<<dim3(12288, 3), 256>>>(W + oWd, W + WTOT + oWd, ddw);

    auto mhaSelf = [&](const __half* xh, const __half* xl, size_t ow, int S, int wnd) {
        int rows = 4 * S;
        GE(xh, xl, ow, nullptr, QKVh, QKVl, rows, 3072, 1024, nullptr, 0);
        attn_tc<<<dim3(S/128, 16, 4), 256, AT_SM>>>(
            QKVh, QKVl, QKVh + 1024, QKVl + 1024, QKVh + 2048, QKVl + 2048,
            A0h, A0l, S, wnd, 3072, 3072);
        GE(A0h, A0l, ow + (size_t)3*HH, bT, nullptr, nullptr, rows, 1024, 1024, nullptr, 0);
    };

    const int encS[4] = {1024, 1024, 512, 256};
    float* Zp[4] = {Z0, Z1, Z2, Z3};
    for (int i = 0; i < 4; i++) {
        int S = encS[i], rows = 4 * S;
        mhaSelf(Ash, Asl, oE + (size_t)i*4*HH, S, 1);
        const float* lnb = enc_ln + (size_t)i * 4096;
        ln_kernel<<<rows, 256>>>(bY, bX, bT, lnb, lnb + 1024, Ash, Asl);
        GE(Ash, Asl, oF1e + (size_t)i*4*HH, nullptr, im, imL, rows, 4096, 1024,
           eb1 + (size_t)i*4096, 1);
        GE(im, imL, oF2e + (size_t)i*4*HH, bT, nullptr, nullptr, rows, 1024, 4096,
           eb2 + (size_t)i*1024, 0);
        ln_kernel<<<rows, 256>>>(Zp[i], bY, bT, lnb + 2048, lnb + 3072,
                                 Zsh + zo[i], Zsl + zo[i]);
        if (i == 0) {
            im2col_split_kernel<<<(rows*3072/4 + 255)/256, 256>>>(im, imL, Zp[i], S, S, 1024,
                                                                  1, 0, rows*3072/4);
            GE(im, imL, oWc, bX, Ash, Asl, rows, 1024, 3072, conv0_b, 1);
        } else if (i < 3) {
            int S2 = S/2, n4 = 4*S2*256;
            poolrelu_kernel<<<(n4 + 255)/256, 256>>>(bX, Ash, Asl, Zp[i], S2, n4);
        }
    }

    mhaSelf(Zsh + zo[3], Zsl + zo[3], oD0, 256, 0);
    ln_kernel<<<1024, 256>>>(FD0, Z3, bT, dln0, dln0 + 1024, nullptr, nullptr);

    const float* fdPrev = FD0; int Sprev = 256;
    const float* feP[3] = {Z2, Z1, Z0};
    const size_t feZ[3] = {zo[2], zo[1], zo[0]};
    const int decS[3] = {512, 1024, 1024}, decSt[3] = {2, 2, 1};
    float* fdOut[3] = {FD1, FD2, FD3};
    for (int i = 0; i < 3; i++) {
        int S = decS[i], rows = 4 * S;
        im2col_split_kernel<<<(rows*3072/4 + 255)/256, 256>>>(im, imL, fdPrev, S, Sprev, 1024,
                                                              decSt[i], 1, rows*3072/4);
        GE(im, imL, oWd + (size_t)i*3*HH, bD, Ash, Asl, rows, 1024, 3072,
           ddb + (size_t)i*1024, 1);
        const float* lnb = dln + (size_t)i * 6144;
        const size_t a1 = oD1 + (size_t)i*4*HH, a2 = oD2 + (size_t)i*4*HH;
        // dual Q: chain0 = fe @ Wq(a1), chain1 = fd @ Wq(a2)
        GE2(Zsh + feZ[i], Zsl + feZ[i], a1, nullptr, Q0h, Q0l,
            Ash, Asl,                   a2, nullptr, Q1h, Q1l, rows, 1024, 1024);
        // dual KV: chain0 = fd @ Wkv(a1), chain1 = fe @ Wkv(a2)
        GE2(Ash, Asl,                   a1 + (size_t)HH, nullptr, KV0h, KV0l,
            Zsh + feZ[i], Zsl + feZ[i], a2 + (size_t)HH, nullptr, KV1h, KV1l,
            rows, 2048, 1024);
        attn_tc_dual<<<dim3(S/128, 16, 8), 256, AT_SM>>>(
            Q0h, Q0l, KV0h, KV0l, KV0h + 1024, KV0l + 1024, A0h, A0l,
            Q1h, Q1l, KV1h, KV1l, KV1h + 1024, KV1l + 1024, A1h, A1l, S);
        // dual O projections
        GE2(A0h, A0l, a1 + (size_t)3*HH, bT,  nullptr, nullptr,
            A1h, A1l, a2 + (size_t)3*HH, bT2, nullptr, nullptr, rows, 1024, 1024);
        // dual LN: X2 = LN(fe + bT), Y2 = LN(fd + bT2)
        ln_dual<<<dim3(rows, 2), 256>>>(bY, feP[i], bT, lnb, lnb + 1024,
                                        bY2, bD, bT2, lnb + 2048, lnb + 3072);
        int n4 = rows * 256;
        add_kernel<<<(n4 + 255)/256, 256>>>(bZ, Ash, Asl, bY, bY2, n4);
        GE(Ash, Asl, oF1d + (size_t)i*4*HH, nullptr, im, imL, rows, 4096, 1024,
           db1 + (size_t)i*4096, 1);
        GE(im, imL, oF2d + (size_t)i*4*HH, bT, nullptr, nullptr, rows, 1024, 4096,
           db2 + (size_t)i*1024, 0);
        ln_kernel<<<rows, 256>>>(fdOut[i], bZ, bT, lnb + 4096, lnb + 5120, nullptr, nullptr);
        fdPrev = fdOut[i]; Sprev = S;
    }
}